// round 13
// baseline (speedup 1.0000x reference)
#include <cuda_runtime.h>
#include <cstdint>

#define BB 32
#define SS 256
#define TT 128
#define EENC 512
#define HH 512
#define EEMB 256
#define VV 32000
#define K0 1280
#define K1 1024
#define KL 1024
#define OUT_TAIL_OFF 131072000ll

__device__ float g_keyproj[BB*SS*HH];
__device__ float g_Wcat0[2048*K0];   // col order: [ctx(512) | emb(256) | h0(512)]
__device__ float g_Wcat1[2048*K1];   // col order: [h0(512) | h1(512)]
__device__ float g_bcat0[2048];
__device__ float g_bcat1[2048];
__device__ float g_Wqt[HH*HH];
__device__ float g_Wt32[(size_t)VV*KL];
__device__ float g_xcat0[BB*K0];     // [ctx | emb | h0]
__device__ float g_xcat1[BB*K1];     // [h0 | h1]
__device__ float g_part0[10*BB*2048];
__device__ float g_part1[8*BB*2048];
__device__ float g_h1[BB*HH];
__device__ float g_c0[BB*HH];
__device__ float g_c1[BB*HH];
__device__ float g_qp[BB*HH];
__device__ float g_scores[BB*SS];
__device__ float g_Xall[(size_t)BB*TT*KL];
__device__ unsigned g_cnt[64];   // [32]=gates0 tiles done, [33]=gates1 tiles done

__device__ __forceinline__ float tanh_acc(float x){
    float xx = fminf(15.f, fmaxf(-15.f, x));
    float e  = __expf(2.f*xx);
    return 1.f - __fdividef(2.f, e + 1.f);
}
__device__ __forceinline__ float sigf(float x){
    float xx = fminf(30.f, fmaxf(-30.f, x));
    return __fdividef(1.f, 1.f + __expf(-xx));
}
__device__ __forceinline__ float tanh_fast(float x){
    float y; asm("tanh.approx.f32 %0, %1;" : "=f"(y) : "f"(x));
    return y;
}
__device__ __forceinline__ float tf32r(float x){
    unsigned u; asm("cvt.rna.tf32.f32 %0, %1;" : "=r"(u) : "f"(x));
    return __uint_as_float(u);
}
__device__ __forceinline__ void signal(unsigned* c){
    __syncthreads();
    if (threadIdx.x == 0){ __threadfence(); atomicAdd(c, 1u); }
}
__device__ __forceinline__ void wait_for(unsigned* c, unsigned tgt){
    if (threadIdx.x == 0){
        while (*(volatile unsigned*)c < tgt) __nanosleep(64);
        __threadfence();
    }
    __syncthreads();
}

__global__ void init_kernel(const float* __restrict__ Wih0, const float* __restrict__ Whh0,
                            const float* __restrict__ bih0, const float* __restrict__ bhh0,
                            const float* __restrict__ Wih1, const float* __restrict__ Whh1,
                            const float* __restrict__ bih1, const float* __restrict__ bhh1,
                            const float* __restrict__ Wq,   const float* __restrict__ bq,
                            const int* __restrict__ tok,    const float* __restrict__ emb)
{
    const int NW0=2048*K0, NW1=2048*K1, NB=2048, NWQ=HH*HH, NQP=BB*HH;
    const int NZ = BB*HH*3 + BB*K0 + BB*K1 + 64;
    const int TOT = NW0+NW1+2*NB+NWQ+NQP+NZ;
    for (int idx = blockIdx.x*blockDim.x+threadIdx.x; idx < TOT; idx += gridDim.x*blockDim.x){
        int r = idx;
        if (r < NW0){
            int j=r/K0,k=r%K0;
            float w;
            if (k < 512)       w = Wih0[j*768 + 256 + k];        // ctx
            else if (k < 768)  w = Wih0[j*768 + (k-512)];        // emb
            else               w = Whh0[j*512 + (k-768)];        // h0
            g_Wcat0[r] = w; continue;
        }
        r -= NW0;
        if (r < NW1){ int j=r/K1,k=r%K1; g_Wcat1[r]=(k<512)?Wih1[j*512+k]:Whh1[j*512+(k-512)]; continue; }
        r -= NW1;
        if (r < NB){ g_bcat0[r]=bih0[r]+bhh0[r]; continue; }
        r -= NB;
        if (r < NB){ g_bcat1[r]=bih1[r]+bhh1[r]; continue; }
        r -= NB;
        if (r < NWQ){ int k=r/HH,h=r%HH; g_Wqt[r]=Wq[h*HH+k]; continue; }
        r -= NWQ;
        if (r < NQP){ g_qp[r]=bq[r%HH]; continue; }
        r -= NQP;
        if (r < BB*HH){ g_h1[r]=0.f; continue; }
        r -= BB*HH;
        if (r < BB*HH){ g_c0[r]=0.f; continue; }
        r -= BB*HH;
        if (r < BB*HH){ g_c1[r]=0.f; continue; }
        r -= BB*HH;
        if (r < BB*K0){
            int b=r/K0, k=r%K0;
            g_xcat0[r] = (k>=512 && k<768) ? emb[(size_t)tok[b*TT]*EEMB + (k-512)] : 0.f;
            continue;
        }
        r -= BB*K0;
        if (r < BB*K1){ g_xcat1[r]=0.f; continue; }
        r -= BB*K1;
        g_cnt[r] = 0u;
    }
}

__global__ void cvt_wout(const float* __restrict__ Wout)
{
    size_t n = (size_t)VV*KL/4;
    for (size_t i = blockIdx.x*blockDim.x+threadIdx.x; i < n; i += (size_t)gridDim.x*blockDim.x){
        float4 v = reinterpret_cast<const float4*>(Wout)[i];
        v.x=tf32r(v.x); v.y=tf32r(v.y); v.z=tf32r(v.z); v.w=tf32r(v.w);
        reinterpret_cast<float4*>(g_Wt32)[i] = v;
    }
}

// fp32 GEMM for keyproj: C = A@B^T + bias
template<int BM,int BN,int BK,int TM,int TN,int THREADS>
__global__ __launch_bounds__(THREADS) void gemm_tn(
    const float* __restrict__ A, const float* __restrict__ B,
    const float* __restrict__ bias, float* __restrict__ C, int M, int N, int K)
{
    constexpr int AF4 = BM*BK/(4*THREADS);
    constexpr int BF4 = BN*BK/(4*THREADS);
    constexpr int KC4 = BK/4;
    constexpr int NT  = BN/TN;
    __shared__ __align__(16) float As[2][BK][BM];
    __shared__ __align__(16) float Bs[2][BK][BN];
    const int tid = threadIdx.x;
    const int tm = (tid/NT)*TM, tn = (tid%NT)*TN;
    const size_t m0 = (size_t)blockIdx.y*BM, n0 = (size_t)blockIdx.x*BN;
    const float* Ab = A + m0*K;
    const float* Bb = B + n0*K;
    float acc[TM][TN];
#pragma unroll
    for (int i=0;i<TM;i++)
#pragma unroll
        for (int j=0;j<TN;j++) acc[i][j]=0.f;
    float4 ra[AF4], rb[BF4];
#pragma unroll
    for (int i=0;i<AF4;i++){ int f=tid+i*THREADS,r=f/KC4,c=f%KC4;
        ra[i]=*reinterpret_cast<const float4*>(Ab+(size_t)r*K+c*4); }
#pragma unroll
    for (int i=0;i<BF4;i++){ int f=tid+i*THREADS,r=f/KC4,c=f%KC4;
        rb[i]=*reinterpret_cast<const float4*>(Bb+(size_t)r*K+c*4); }
#pragma unroll
    for (int i=0;i<AF4;i++){ int f=tid+i*THREADS,r=f/KC4,c=f%KC4;
        As[0][c*4+0][r]=ra[i].x; As[0][c*4+1][r]=ra[i].y; As[0][c*4+2][r]=ra[i].z; As[0][c*4+3][r]=ra[i].w; }
#pragma unroll
    for (int i=0;i<BF4;i++){ int f=tid+i*THREADS,r=f/KC4,c=f%KC4;
        Bs[0][c*4+0][r]=rb[i].x; Bs[0][c*4+1][r]=rb[i].y; Bs[0][c*4+2][r]=rb[i].z; Bs[0][c*4+3][r]=rb[i].w; }
    __syncthreads();
    const int KT = K/BK;
    for (int kt=0; kt<KT; ++kt){
        const int cur = kt&1;
        const bool nx = (kt+1<KT);
        if (nx){
            const float* A2 = Ab+(size_t)(kt+1)*BK;
            const float* B2 = Bb+(size_t)(kt+1)*BK;
#pragma unroll
            for (int i=0;i<AF4;i++){ int f=tid+i*THREADS,r=f/KC4,c=f%KC4;
                ra[i]=*reinterpret_cast<const float4*>(A2+(size_t)r*K+c*4); }
#pragma unroll
            for (int i=0;i<BF4;i++){ int f=tid+i*THREADS,r=f/KC4,c=f%KC4;
                rb[i]=*reinterpret_cast<const float4*>(B2+(size_t)r*K+c*4); }
        }
#pragma unroll
        for (int k=0;k<BK;k++){
            float a[TM], b[TN];
#pragma unroll
            for (int i=0;i<TM/4;i++){ float4 t=*reinterpret_cast<const float4*>(&As[cur][k][tm+i*4]);
                a[i*4]=t.x;a[i*4+1]=t.y;a[i*4+2]=t.z;a[i*4+3]=t.w; }
#pragma unroll
            for (int j=0;j<TN/4;j++){ float4 t=*reinterpret_cast<const float4*>(&Bs[cur][k][tn+j*4]);
                b[j*4]=t.x;b[j*4+1]=t.y;b[j*4+2]=t.z;b[j*4+3]=t.w; }
#pragma unroll
            for (int i=0;i<TM;i++)
#pragma unroll
                for (int j=0;j<TN;j++) acc[i][j]=fmaf(a[i],b[j],acc[i][j]);
        }
        if (nx){
            const int nb = cur^1;
#pragma unroll
            for (int i=0;i<AF4;i++){ int f=tid+i*THREADS,r=f/KC4,c=f%KC4;
                As[nb][c*4+0][r]=ra[i].x; As[nb][c*4+1][r]=ra[i].y; As[nb][c*4+2][r]=ra[i].z; As[nb][c*4+3][r]=ra[i].w; }
#pragma unroll
            for (int i=0;i<BF4;i++){ int f=tid+i*THREADS,r=f/KC4,c=f%KC4;
                Bs[nb][c*4+0][r]=rb[i].x; Bs[nb][c*4+1][r]=rb[i].y; Bs[nb][c*4+2][r]=rb[i].z; Bs[nb][c*4+3][r]=rb[i].w; }
            __syncthreads();
        }
    }
#pragma unroll
    for (int i=0;i<TM;i++)
#pragma unroll
        for (int j=0;j<TN;j++){
            size_t cn = n0+tn+j;
            C[(m0+tm+i)*(size_t)N+cn] = acc[i][j] + bias[cn];
        }
}

// scores: one warp per (b, s); grid (32, 32), 8 warps/block  [round-8 proven]
__global__ __launch_bounds__(256) void scores_kernel(const float* __restrict__ v)
{
    const int b = blockIdx.x, tid = threadIdx.x;
    const int w = tid>>5, lane = tid&31;
    __shared__ __align__(16) float qs[512], vsm[512];
    qs[tid]      = g_qp[b*HH+tid];
    qs[tid+256]  = g_qp[b*HH+tid+256];
    vsm[tid]     = v[tid];
    vsm[tid+256] = v[tid+256];
    __syncthreads();
    const int s = blockIdx.y*8 + w;
    const float* kp = g_keyproj + ((size_t)(b*SS+s))*HH;
    float acc = 0.f;
#pragma unroll
    for (int i=0;i<4;i++){
        int h = i*128 + lane*4;
        float4 k4 = *reinterpret_cast<const float4*>(kp + h);
        float4 q4 = *reinterpret_cast<const float4*>(&qs[h]);
        float4 v4 = *reinterpret_cast<const float4*>(&vsm[h]);
        acc = fmaf(v4.x, tanh_fast(k4.x+q4.x), acc);
        acc = fmaf(v4.y, tanh_fast(k4.y+q4.y), acc);
        acc = fmaf(v4.z, tanh_fast(k4.z+q4.z), acc);
        acc = fmaf(v4.w, tanh_fast(k4.w+q4.w), acc);
    }
#pragma unroll
    for (int o=16;o;o>>=1) acc += __shfl_xor_sync(0xffffffffu, acc, o);
    if (lane == 0) g_scores[b*SS+s] = acc;
}

// softmax (redundant per block) + 64-col context chunk; grid (32, 8)  [round-8 proven]
__global__ __launch_bounds__(256) void smctx_kernel(const float* __restrict__ enc, int t)
{
    const int b = blockIdx.x, chunk = blockIdx.y, tid = threadIdx.x;
    const int w = tid>>5, lane = tid&31;
    __shared__ __align__(16) float wsm[SS];
    __shared__ __align__(16) float cpart[4][64];
    __shared__ float red[8];
    __shared__ float smax_s, sinv_s;
    float x = g_scores[b*SS+tid];
    float m = x;
#pragma unroll
    for (int o=16;o;o>>=1) m = fmaxf(m, __shfl_xor_sync(0xffffffffu, m, o));
    if (lane==0) red[w]=m;
    __syncthreads();
    if (tid==0){ float mm=red[0];
#pragma unroll
        for (int i=1;i<8;i++) mm=fmaxf(mm,red[i]); smax_s=mm; }
    __syncthreads();
    float ex = __expf(x - smax_s);
    float s2 = ex;
#pragma unroll
    for (int o=16;o;o>>=1) s2 += __shfl_xor_sync(0xffffffffu, s2, o);
    if (lane==0) red[w]=s2;
    __syncthreads();
    if (tid==0){ float ss=0.f;
#pragma unroll
        for (int i=0;i<8;i++) ss+=red[i]; sinv_s=1.f/ss; }
    __syncthreads();
    wsm[tid] = ex*sinv_s;
    __syncthreads();
    const int el = tid & 63, sq = tid >> 6;
    const int e = chunk*64 + el;
    const float* eb = enc + ((size_t)(b*SS) + sq*64)*EENC + e;
    float acc = 0.f;
#pragma unroll 4
    for (int s=0;s<64;s++) acc = fmaf(wsm[sq*64+s], eb[(size_t)s*EENC], acc);
    cpart[sq][el] = acc;
    __syncthreads();
    if (tid < 64){
        float ctx = cpart[0][tid]+cpart[1][tid]+cpart[2][tid]+cpart[3][tid];
        g_xcat0[b*K0 + e] = ctx;
        g_Xall[((size_t)(b*TT+t))*KL + 512 + e] = tf32r(ctx);
    }
}

// one 32(m) x 64(j) x 128(k) gates tile; 256 threads; smem from sbuf
__device__ __forceinline__ void gates_tile64(
    const float* __restrict__ X, const float* __restrict__ W,
    float* __restrict__ out, int K, int j0, int k0, float* sbuf)
{
    float (*As)[16][32] = reinterpret_cast<float(*)[16][32]>(sbuf);
    float (*Bs)[16][68] = reinterpret_cast<float(*)[16][68]>(sbuf + 1024);
    const int tid = threadIdx.x;
    const int tm = (tid>>4)*2, tn = (tid&15)*4;
    float acc[2][4] = {};
    float4 ra, rb;
    if (tid < 128){ int r=tid>>2,c=tid&3;
        ra = *reinterpret_cast<const float4*>(X+(size_t)r*K+k0+c*4); }
    { int r=tid>>2,c=tid&3;
        rb = *reinterpret_cast<const float4*>(W+(size_t)(j0+r)*K+k0+c*4); }
    if (tid < 128){ int r=tid>>2,c=tid&3;
        As[0][c*4+0][r]=ra.x; As[0][c*4+1][r]=ra.y; As[0][c*4+2][r]=ra.z; As[0][c*4+3][r]=ra.w; }
    { int r=tid>>2,c=tid&3;
        Bs[0][c*4+0][r]=rb.x; Bs[0][c*4+1][r]=rb.y; Bs[0][c*4+2][r]=rb.z; Bs[0][c*4+3][r]=rb.w; }
    __syncthreads();
    for (int kt=0; kt<8; ++kt){
        const int buf = kt&1;
        const bool nx = (kt<7);
        if (nx){
            int kk = k0 + (kt+1)*16;
            if (tid < 128){ int r=tid>>2,c=tid&3;
                ra = *reinterpret_cast<const float4*>(X+(size_t)r*K+kk+c*4); }
            { int r=tid>>2,c=tid&3;
                rb = *reinterpret_cast<const float4*>(W+(size_t)(j0+r)*K+kk+c*4); }
        }
#pragma unroll
        for (int k=0;k<16;k++){
            float2 a2 = *reinterpret_cast<const float2*>(&As[buf][k][tm]);
            float4 b4 = *reinterpret_cast<const float4*>(&Bs[buf][k][tn]);
            float av[2]={a2.x,a2.y}, bv[4]={b4.x,b4.y,b4.z,b4.w};
#pragma unroll
            for (int i=0;i<2;i++)
#pragma unroll
                for (int j=0;j<4;j++) acc[i][j]=fmaf(av[i],bv[j],acc[i][j]);
        }
        if (nx){
            const int nb = buf^1;
            if (tid < 128){ int r=tid>>2,c=tid&3;
                As[nb][c*4+0][r]=ra.x; As[nb][c*4+1][r]=ra.y; As[nb][c*4+2][r]=ra.z; As[nb][c*4+3][r]=ra.w; }
            { int r=tid>>2,c=tid&3;
                Bs[nb][c*4+0][r]=rb.x; Bs[nb][c*4+1][r]=rb.y; Bs[nb][c*4+2][r]=rb.z; Bs[nb][c*4+3][r]=rb.w; }
            __syncthreads();
        }
    }
#pragma unroll
    for (int i=0;i<2;i++)
#pragma unroll
        for (int j=0;j<4;j++)
            out[(tm+i)*2048 + j0+tn+j] = acc[i][j];
}

// gatecell0: 320 gates0 tiles (full K0, signal) + 32 cell0 waiters; 352 blocks = one wave
__global__ __launch_bounds__(256) void gatecell0(int t)
{
    __shared__ __align__(16) float sbuf[3200];
    const int bi = blockIdx.x, tid = threadIdx.x;
    if (bi < 320){
        const int chunk = bi>>5, j0 = (bi&31)*64;
        gates_tile64(g_xcat0, g_Wcat0, g_part0 + chunk*65536, K0, j0, chunk*128, sbuf);
        signal(&g_cnt[32]);
    } else {
        const int b = bi - 320;
        wait_for(&g_cnt[32], (unsigned)(t+1)*320u);
#pragma unroll
        for (int uu=0; uu<2; uu++){
            const int u = tid + uu*256;
            float gi=g_bcat0[u], gf=g_bcat0[512+u], gg=g_bcat0[1024+u], go=g_bcat0[1536+u];
#pragma unroll
            for (int s=0;s<10;s++){
                const float* p = g_part0 + s*65536 + b*2048;
                gi += p[u]; gf += p[512+u]; gg += p[1024+u]; go += p[1536+u];
            }
            float c = sigf(gf)*g_c0[b*HH+u] + sigf(gi)*tanh_acc(gg);
            float h = sigf(go)*tanh_acc(c);
            g_c0[b*HH+u] = c;
            g_xcat0[b*K0 + 768 + u] = h;
            g_xcat1[b*K1 + u]       = h;
        }
    }
}

// gatecell1: 256 gates1 tiles (full K1, signal) + 32 cell1 waiters (qproj + emb prefetch)
__global__ __launch_bounds__(256) void gatecell1(
    const float* __restrict__ bq, const int* __restrict__ tok,
    const float* __restrict__ emb, int t)
{
    __shared__ __align__(16) float sbuf[3200];
    const int bi = blockIdx.x, tid = threadIdx.x;
    if (bi < 256){
        const int chunk = bi>>5, j0 = (bi&31)*64;
        gates_tile64(g_xcat1, g_Wcat1, g_part1 + chunk*65536, K1, j0, chunk*128, sbuf);
        signal(&g_cnt[33]);
    } else {
        const int b = bi - 256;
        float* h1s   = sbuf;          // 512
        float* qpart = sbuf + 512;    // 2048
        wait_for(&g_cnt[33], (unsigned)(t+1)*256u);
#pragma unroll
        for (int uu=0; uu<2; uu++){
            const int u = tid + uu*256;
            float gi=g_bcat1[u], gf=g_bcat1[512+u], gg=g_bcat1[1024+u], go=g_bcat1[1536+u];
#pragma unroll
            for (int s=0;s<8;s++){
                const float* p = g_part1 + s*65536 + b*2048;
                gi += p[u]; gf += p[512+u]; gg += p[1024+u]; go += p[1536+u];
            }
            float c = sigf(gf)*g_c1[b*HH+u] + sigf(gi)*tanh_acc(gg);
            float h = sigf(go)*tanh_acc(c);
            g_c1[b*HH+u] = c;
            g_h1[b*HH+u] = h;
            g_xcat1[b*K1 + 512 + u] = h;
            g_Xall[((size_t)(b*TT+t))*KL + u] = tf32r(h);
            h1s[u] = h;
        }
        if (t+1 < TT){
            int row = tok[b*TT + t + 1];
            g_xcat0[b*K0 + 512 + tid] = emb[(size_t)row*EEMB + tid];
        }
        __syncthreads();
#pragma unroll
        for (int uu=0; uu<2; uu++){
            const int u = tid + uu*256;
            const int h4 = (u & 127)*4, kp = u >> 7;
            float4 a = make_float4(0.f,0.f,0.f,0.f);
            const float* wb = g_Wqt + (size_t)kp*128*HH + h4;
#pragma unroll 4
            for (int k=0;k<128;k++){
                float4 w4 = *reinterpret_cast<const float4*>(wb + (size_t)k*HH);
                float xv = h1s[kp*128 + k];
                a.x=fmaf(w4.x,xv,a.x); a.y=fmaf(w4.y,xv,a.y);
                a.z=fmaf(w4.z,xv,a.z); a.w=fmaf(w4.w,xv,a.w);
            }
            *reinterpret_cast<float4*>(&qpart[kp*512 + h4]) = a;
        }
        __syncthreads();
#pragma unroll
        for (int uu=0; uu<2; uu++){
            const int u = tid + uu*256;
            g_qp[b*HH+u] = qpart[u]+qpart[512+u]+qpart[1024+u]+qpart[1536+u] + bq[u];
        }
    }
}

// logits: tf32 mma.sync, BM128 x BN128 x BK16, 8 warps; grid (M/128, N/128) m-major
__global__ __launch_bounds__(256) void logits_mma(
    const float* __restrict__ A, const float* __restrict__ B,
    const float* __restrict__ bias, float* __restrict__ C)
{
    __shared__ __align__(16) float As[2][128][20];
    __shared__ __align__(16) float Bs[2][128][20];
    const int tid = threadIdx.x, lane = tid&31, w = tid>>5;
    const int wm = (w&3)*32, wn = (w>>2)*64;
    const int m0 = blockIdx.x*128, n0 = blockIdx.y*128;
    const int lr = lane>>2, lc = lane&3;
    float d[2][8][4] = {};

#define STAGE(bufi, kt) do { \
    int kk = (kt)*16; \
    _Pragma("unroll") \
    for (int i=0;i<2;i++){ \
        int f = tid + i*256; int r = f>>2, c = f&3; \
        unsigned dst = (unsigned)__cvta_generic_to_shared(&As[bufi][r][c*4]); \
        const float* src = A + (size_t)(m0+r)*KL + kk + c*4; \
        asm volatile("cp.async.cg.shared.global [%0], [%1], 16;"::"r"(dst),"l"(src)); \
    } \
    _Pragma("unroll") \
    for (int i=0;i<2;i++){ \
        int f = tid + i*256; int r = f>>2, c = f&3; \
        unsigned dst = (unsigned)__cvta_generic_to_shared(&Bs[bufi][r][c*4]); \
        const float* src = B + (size_t)(n0+r)*KL + kk + c*4; \
        asm volatile("cp.async.cg.shared.global [%0], [%1], 16;"::"r"(dst),"l"(src)); \
    } \
    asm volatile("cp.async.commit_group;"); \
} while(0)

    STAGE(0, 0);
    const int KT = KL/16;
    for (int kt=0; kt<KT; ++kt){
        const int buf = kt&1;
        if (kt+1 < KT){ STAGE(buf^1, kt+1); asm volatile("cp.async.wait_group 1;"); }
        else          { asm volatile("cp.async.wait_group 0;"); }
        __syncthreads();
#pragma unroll
        for (int k8=0;k8<2;k8++){
            const int co = k8*8;
            unsigned a[2][4];
#pragma unroll
            for (int mi=0;mi<2;mi++){
                int rb = wm + mi*16 + lr;
                a[mi][0] = __float_as_uint(As[buf][rb  ][co+lc]);
                a[mi][1] = __float_as_uint(As[buf][rb+8][co+lc]);
                a[mi][2] = __float_as_uint(As[buf][rb  ][co+lc+4]);
                a[mi][3] = __float_as_uint(As[buf][rb+8][co+lc+4]);
            }
#pragma unroll
            for (int nj=0;nj<8;nj++){
                int nb = wn + nj*8 + lr;
                unsigned b0 = __float_as_uint(Bs[buf][nb][co+lc]);
                unsigned b1 = __float_as_uint(Bs[buf][nb][co+lc+4]);
#pragma unroll
                for (int mi=0;mi<2;mi++){
                    asm volatile(
                      "mma.sync.aligned.m16n8k8.row.col.f32.tf32.tf32.f32 "
                      "{%0,%1,%2,%3},{%4,%5,%6,%7},{%8,%9},{%0,%1,%2,%3};"
                      : "+f"(d[mi][nj][0]),"+f"(d[mi][nj][1]),"+f"(d[mi][nj][2]),"+f"(d[mi][nj][3])
                      : "r"(a[mi][0]),"r"(a[mi][1]),"r"(a[mi][2]),"r"(a[mi][3]),"r"(b0),"r"(b1));
                }
            }
        }
        __syncthreads();
    }
#undef STAGE

    float* ep = &As[0][0][0] + w*640;
#pragma unroll
    for (int h=0; h<4; h++){
#pragma unroll
        for (int mi=0;mi<2;mi++){
#pragma unroll
            for (int njl=0;njl<2;njl++){
                int nj = h*2 + njl;
                int r0 = mi*16 + lr;
                ep[ r0   *20 + njl*8 + lc*2    ] = d[mi][nj][0];
                ep[ r0   *20 + njl*8 + lc*2 + 1] = d[mi][nj][1];
                ep[(r0+8)*20 + njl*8 + lc*2    ] = d[mi][nj][2];
                ep[(r0+8)*20 + njl*8 + lc*2 + 1] = d[mi][nj][3];
            }
        }
        __syncwarp();
#pragma unroll
        for (int q=0;q<4;q++){
            int idx = q*32 + lane;
            int r = idx>>2, c4 = idx&3;
            float4 vv = *reinterpret_cast<float4*>(&ep[r*20 + c4*4]);
            size_t nn = (size_t)n0 + wn + h*16 + c4*4;
            float4 bb = *reinterpret_cast<const float4*>(&bias[nn]);
            vv.x+=bb.x; vv.y+=bb.y; vv.z+=bb.z; vv.w+=bb.w;
            *reinterpret_cast<float4*>(&C[(size_t)(m0+wm+r)*VV + nn]) = vv;
        }
        __syncwarp();
    }
}

__global__ __launch_bounds__(512) void tail_kernel(float* __restrict__ out)
{
    int idx = blockIdx.x*blockDim.x + threadIdx.x;
    int part = idx / (BB*HH);
    int off  = idx % (BB*HH);
    int b = off / HH, u = off % HH;
    float val;
    if      (part == 0) val = g_xcat1[b*K1 + u];
    else if (part == 1) val = g_h1[off];
    else if (part == 2) val = g_c0[off];
    else                val = g_c1[off];
    out[OUT_TAIL_OFF + idx] = val;
}

extern "C" void kernel_launch(void* const* d_in, const int* in_sizes, int n_in,
                              void* d_out, int out_size)
{
    const float* enc  = (const float*)d_in[0];
    const int*   tok  = (const int*)  d_in[1];
    const float* emb  = (const float*)d_in[2];
    const float* Wq   = (const float*)d_in[3];
    const float* bq   = (const float*)d_in[4];
    const float* Wk   = (const float*)d_in[5];
    const float* bk   = (const float*)d_in[6];
    const float* v    = (const float*)d_in[7];
    const float* Wih0 = (const float*)d_in[8];
    const float* Whh0 = (const float*)d_in[9];
    const float* bih0 = (const float*)d_in[10];
    const float* bhh0 = (const float*)d_in[11];
    const float* Wih1 = (const float*)d_in[12];
    const float* Whh1 = (const float*)d_in[13];
    const float* bih1 = (const float*)d_in[14];
    const float* bhh1 = (const float*)d_in[15];
    const float* Wout = (const float*)d_in[16];
    const float* bout = (const float*)d_in[17];
    float* out = (float*)d_out;

    float *p_keyproj, *p_Wt32, *p_Xall;
    cudaGetSymbolAddress((void**)&p_keyproj, g_keyproj);
    cudaGetSymbolAddress((void**)&p_Wt32,   g_Wt32);
    cudaGetSymbolAddress((void**)&p_Xall,   g_Xall);

    init_kernel<<<2048, 256>>>(Wih0, Whh0, bih0, bhh0, Wih1, Whh1, bih1, bhh1, Wq, bq, tok, emb);
    cvt_wout<<<2048, 256>>>(Wout);

    {   // key_proj = enc(8192x512) @ Wk^T + bk
        dim3 grid(HH/64, (BB*SS)/64);
        gemm_tn<64,64,16,4,4,256><<<grid, 256>>>(enc, Wk, bk, p_keyproj, BB*SS, HH, EENC);
    }

    for (int t = 0; t < TT; ++t){
        scores_kernel<<<dim3(BB, 32), 256>>>(v);
        smctx_kernel<<<dim3(BB, 8), 256>>>(enc, t);
        gatecell0<<<352, 256>>>(t);
        gatecell1<<<288, 256>>>(bq, tok, emb, t);
    }

    {   // logits = Xall(4096x1024) @ Wt32^T + bout  (m-major grid for B-tile reuse)
        dim3 grid((BB*TT)/128, VV/128);
        logits_mma<<<grid, 256>>>(p_Xall, p_Wt32, bout, out);
    }
    tail_kernel<<<128, 512>>>(out);
}

// round 14
// speedup vs baseline: 1.2997x; 1.2997x over previous
#include <cuda_runtime.h>
#include <cuda_fp16.h>
#include <cstdint>

#define BB 32
#define SS 256
#define TT 128
#define EENC 512
#define HH 512
#define EEMB 256
#define VV 32000
#define K0 1280
#define K1 1024
#define KL 1024
#define OUT_TAIL_OFF 131072000ll

__device__ float  g_keyproj[BB*SS*HH];
__device__ __half g_kph[BB*SS*HH];
__device__ float g_W0hi[2048*K0];
__device__ float g_W0lo[2048*K0];
__device__ float g_W1hi[2048*K1];
__device__ float g_W1lo[2048*K1];
__device__ float g_bcat0[2048];
__device__ float g_bcat1[2048];
__device__ float g_Wqt[HH*HH];
__device__ float g_Wt32[(size_t)VV*KL];
__device__ float g_xcat0[BB*K0];   // [emb | ctx | h0]
__device__ float g_xcat1[BB*K1];   // [h0 | h1]
__device__ float g_part0[10*BB*2048];
__device__ float g_part1[8*BB*2048];
__device__ float g_h1[BB*HH];
__device__ float g_c0[BB*HH];
__device__ float g_c1[BB*HH];
__device__ float g_qp[BB*HH];
__device__ float g_scores[BB*SS];
__device__ float g_Xall[(size_t)BB*TT*KL];

__device__ __forceinline__ float tanh_acc(float x){
    float xx = fminf(15.f, fmaxf(-15.f, x));
    float e  = __expf(2.f*xx);
    return 1.f - __fdividef(2.f, e + 1.f);
}
__device__ __forceinline__ float sigf(float x){
    float xx = fminf(30.f, fmaxf(-30.f, x));
    return __fdividef(1.f, 1.f + __expf(-xx));
}
__device__ __forceinline__ float tanh_fast(float x){
    float y; asm("tanh.approx.f32 %0, %1;" : "=f"(y) : "f"(x));
    return y;
}
__device__ __forceinline__ float tf32r(float x){
    unsigned u; asm("cvt.rna.tf32.f32 %0, %1;" : "=r"(u) : "f"(x));
    return __uint_as_float(u);
}

__global__ void init_kernel(const float* __restrict__ Wih0, const float* __restrict__ Whh0,
                            const float* __restrict__ bih0, const float* __restrict__ bhh0,
                            const float* __restrict__ Wih1, const float* __restrict__ Whh1,
                            const float* __restrict__ bih1, const float* __restrict__ bhh1,
                            const float* __restrict__ Wq,   const float* __restrict__ bq)
{
    const int NW0=2048*K0, NW1=2048*K1, NB=2048, NWQ=HH*HH, NQP=BB*HH;
    const int NZ = BB*HH*3 + BB*K0 + BB*K1;
    const int TOT = NW0+NW1+2*NB+NWQ+NQP+NZ;
    for (int idx = blockIdx.x*blockDim.x+threadIdx.x; idx < TOT; idx += gridDim.x*blockDim.x){
        int r = idx;
        if (r < NW0){
            int j=r/K0,k=r%K0;
            float w = (k<768) ? Wih0[j*768+k] : Whh0[j*512+(k-768)];
            float hi = tf32r(w);
            g_W0hi[r] = hi;
            g_W0lo[r] = tf32r(w - hi);
            continue;
        }
        r -= NW0;
        if (r < NW1){
            int j=r/K1,k=r%K1;
            float w = (k<512) ? Wih1[j*512+k] : Whh1[j*512+(k-512)];
            float hi = tf32r(w);
            g_W1hi[r] = hi;
            g_W1lo[r] = tf32r(w - hi);
            continue;
        }
        r -= NW1;
        if (r < NB){ g_bcat0[r]=bih0[r]+bhh0[r]; continue; }
        r -= NB;
        if (r < NB){ g_bcat1[r]=bih1[r]+bhh1[r]; continue; }
        r -= NB;
        if (r < NWQ){ int k=r/HH,h=r%HH; g_Wqt[r]=Wq[h*HH+k]; continue; }
        r -= NWQ;
        if (r < NQP){ g_qp[r]=bq[r%HH]; continue; }
        r -= NQP;
        if (r < BB*HH){ g_h1[r]=0.f; continue; }
        r -= BB*HH;
        if (r < BB*HH){ g_c0[r]=0.f; continue; }
        r -= BB*HH;
        if (r < BB*HH){ g_c1[r]=0.f; continue; }
        r -= BB*HH;
        if (r < BB*K0){ g_xcat0[r]=0.f; continue; }
        r -= BB*K0;
        g_xcat1[r]=0.f;
    }
}

__global__ void cvt_wout(const float* __restrict__ Wout)
{
    size_t n = (size_t)VV*KL/4;
    for (size_t i = blockIdx.x*blockDim.x+threadIdx.x; i < n; i += (size_t)gridDim.x*blockDim.x){
        float4 v = reinterpret_cast<const float4*>(Wout)[i];
        v.x=tf32r(v.x); v.y=tf32r(v.y); v.z=tf32r(v.z); v.w=tf32r(v.w);
        reinterpret_cast<float4*>(g_Wt32)[i] = v;
    }
}

// fp32->fp16 keyproj conversion (one time)
__global__ void cvt_kp()
{
    int n = BB*SS*HH/2;
    for (int i = blockIdx.x*blockDim.x+threadIdx.x; i < n; i += gridDim.x*blockDim.x){
        float2 f = reinterpret_cast<const float2*>(g_keyproj)[i];
        reinterpret_cast<__half2*>(g_kph)[i] = __floats2half2_rn(f.x, f.y);
    }
}

// fp32 GEMM for keyproj: C = A@B^T + bias
template<int BM,int BN,int BK,int TM,int TN,int THREADS>
__global__ __launch_bounds__(THREADS) void gemm_tn(
    const float* __restrict__ A, const float* __restrict__ B,
    const float* __restrict__ bias, float* __restrict__ C, int M, int N, int K)
{
    constexpr int AF4 = BM*BK/(4*THREADS);
    constexpr int BF4 = BN*BK/(4*THREADS);
    constexpr int KC4 = BK/4;
    constexpr int NT  = BN/TN;
    __shared__ __align__(16) float As[2][BK][BM];
    __shared__ __align__(16) float Bs[2][BK][BN];
    const int tid = threadIdx.x;
    const int tm = (tid/NT)*TM, tn = (tid%NT)*TN;
    const size_t m0 = (size_t)blockIdx.y*BM, n0 = (size_t)blockIdx.x*BN;
    const float* Ab = A + m0*K;
    const float* Bb = B + n0*K;
    float acc[TM][TN];
#pragma unroll
    for (int i=0;i<TM;i++)
#pragma unroll
        for (int j=0;j<TN;j++) acc[i][j]=0.f;
    float4 ra[AF4], rb[BF4];
#pragma unroll
    for (int i=0;i<AF4;i++){ int f=tid+i*THREADS,r=f/KC4,c=f%KC4;
        ra[i]=*reinterpret_cast<const float4*>(Ab+(size_t)r*K+c*4); }
#pragma unroll
    for (int i=0;i<BF4;i++){ int f=tid+i*THREADS,r=f/KC4,c=f%KC4;
        rb[i]=*reinterpret_cast<const float4*>(Bb+(size_t)r*K+c*4); }
#pragma unroll
    for (int i=0;i<AF4;i++){ int f=tid+i*THREADS,r=f/KC4,c=f%KC4;
        As[0][c*4+0][r]=ra[i].x; As[0][c*4+1][r]=ra[i].y; As[0][c*4+2][r]=ra[i].z; As[0][c*4+3][r]=ra[i].w; }
#pragma unroll
    for (int i=0;i<BF4;i++){ int f=tid+i*THREADS,r=f/KC4,c=f%KC4;
        Bs[0][c*4+0][r]=rb[i].x; Bs[0][c*4+1][r]=rb[i].y; Bs[0][c*4+2][r]=rb[i].z; Bs[0][c*4+3][r]=rb[i].w; }
    __syncthreads();
    const int KT = K/BK;
    for (int kt=0; kt<KT; ++kt){
        const int cur = kt&1;
        const bool nx = (kt+1<KT);
        if (nx){
            const float* A2 = Ab+(size_t)(kt+1)*BK;
            const float* B2 = Bb+(size_t)(kt+1)*BK;
#pragma unroll
            for (int i=0;i<AF4;i++){ int f=tid+i*THREADS,r=f/KC4,c=f%KC4;
                ra[i]=*reinterpret_cast<const float4*>(A2+(size_t)r*K+c*4); }
#pragma unroll
            for (int i=0;i<BF4;i++){ int f=tid+i*THREADS,r=f/KC4,c=f%KC4;
                rb[i]=*reinterpret_cast<const float4*>(B2+(size_t)r*K+c*4); }
        }
#pragma unroll
        for (int k=0;k<BK;k++){
            float a[TM], b[TN];
#pragma unroll
            for (int i=0;i<TM/4;i++){ float4 t=*reinterpret_cast<const float4*>(&As[cur][k][tm+i*4]);
                a[i*4]=t.x;a[i*4+1]=t.y;a[i*4+2]=t.z;a[i*4+3]=t.w; }
#pragma unroll
            for (int j=0;j<TN/4;j++){ float4 t=*reinterpret_cast<const float4*>(&Bs[cur][k][tn+j*4]);
                b[j*4]=t.x;b[j*4+1]=t.y;b[j*4+2]=t.z;b[j*4+3]=t.w; }
#pragma unroll
            for (int i=0;i<TM;i++)
#pragma unroll
                for (int j=0;j<TN;j++) acc[i][j]=fmaf(a[i],b[j],acc[i][j]);
        }
        if (nx){
            const int nb = cur^1;
#pragma unroll
            for (int i=0;i<AF4;i++){ int f=tid+i*THREADS,r=f/KC4,c=f%KC4;
                As[nb][c*4+0][r]=ra[i].x; As[nb][c*4+1][r]=ra[i].y; As[nb][c*4+2][r]=ra[i].z; As[nb][c*4+3][r]=ra[i].w; }
#pragma unroll
            for (int i=0;i<BF4;i++){ int f=tid+i*THREADS,r=f/KC4,c=f%KC4;
                Bs[nb][c*4+0][r]=rb[i].x; Bs[nb][c*4+1][r]=rb[i].y; Bs[nb][c*4+2][r]=rb[i].z; Bs[nb][c*4+3][r]=rb[i].w; }
            __syncthreads();
        }
    }
#pragma unroll
    for (int i=0;i<TM;i++)
#pragma unroll
        for (int j=0;j<TN;j++){
            size_t cn = n0+tn+j;
            C[(m0+tm+i)*(size_t)N+cn] = acc[i][j] + bias[cn];
        }
}

// scores: one warp per (b, s); grid (32, 32); keyproj read as fp16
__global__ __launch_bounds__(256) void scores_kernel(const float* __restrict__ v)
{
    const int b = blockIdx.x, tid = threadIdx.x;
    const int w = tid>>5, lane = tid&31;
    __shared__ __align__(16) float qs[512], vsm[512];
    qs[tid]      = g_qp[b*HH+tid];
    qs[tid+256]  = g_qp[b*HH+tid+256];
    vsm[tid]     = v[tid];
    vsm[tid+256] = v[tid+256];
    __syncthreads();
    const int s = blockIdx.y*8 + w;
    const __half* kp = g_kph + ((size_t)(b*SS+s))*HH;
    float acc = 0.f;
#pragma unroll
    for (int i=0;i<4;i++){
        int h = i*128 + lane*4;
        uint2 kk = *reinterpret_cast<const uint2*>(kp + h);
        float2 f01 = __half22float2(*reinterpret_cast<const __half2*>(&kk.x));
        float2 f23 = __half22float2(*reinterpret_cast<const __half2*>(&kk.y));
        float4 q4 = *reinterpret_cast<const float4*>(&qs[h]);
        float4 v4 = *reinterpret_cast<const float4*>(&vsm[h]);
        acc = fmaf(v4.x, tanh_fast(f01.x+q4.x), acc);
        acc = fmaf(v4.y, tanh_fast(f01.y+q4.y), acc);
        acc = fmaf(v4.z, tanh_fast(f23.x+q4.z), acc);
        acc = fmaf(v4.w, tanh_fast(f23.y+q4.w), acc);
    }
#pragma unroll
    for (int o=16;o;o>>=1) acc += __shfl_xor_sync(0xffffffffu, acc, o);
    if (lane == 0) g_scores[b*SS+s] = acc;
}

// softmax (redundant per block) + 64-col context chunk + emb gather; grid (32, 8)
__global__ __launch_bounds__(256) void smctx_kernel(
    const float* __restrict__ enc, const int* __restrict__ tok,
    const float* __restrict__ emb, int t)
{
    const int b = blockIdx.x, chunk = blockIdx.y, tid = threadIdx.x;
    const int w = tid>>5, lane = tid&31;
    __shared__ __align__(16) float wsm[SS];
    __shared__ __align__(16) float cpart[4][64];
    __shared__ float red[8];
    __shared__ float smax_s, sinv_s;
    float x = g_scores[b*SS+tid];
    float m = x;
#pragma unroll
    for (int o=16;o;o>>=1) m = fmaxf(m, __shfl_xor_sync(0xffffffffu, m, o));
    if (lane==0) red[w]=m;
    __syncthreads();
    if (tid==0){ float mm=red[0];
#pragma unroll
        for (int i=1;i<8;i++) mm=fmaxf(mm,red[i]); smax_s=mm; }
    __syncthreads();
    float ex = __expf(x - smax_s);
    float s2 = ex;
#pragma unroll
    for (int o=16;o;o>>=1) s2 += __shfl_xor_sync(0xffffffffu, s2, o);
    if (lane==0) red[w]=s2;
    __syncthreads();
    if (tid==0){ float ss=0.f;
#pragma unroll
        for (int i=0;i<8;i++) ss+=red[i]; sinv_s=1.f/ss; }
    __syncthreads();
    wsm[tid] = ex*sinv_s;
    if (chunk == 0){
        int row = tok[b*TT+t];
        g_xcat0[b*K0+tid] = emb[(size_t)row*EEMB+tid];
    }
    __syncthreads();
    const int el = tid & 63, sq = tid >> 6;
    const int e = chunk*64 + el;
    const float* eb = enc + ((size_t)(b*SS) + sq*64)*EENC + e;
    float acc = 0.f;
#pragma unroll 4
    for (int s=0;s<64;s++) acc = fmaf(wsm[sq*64+s], eb[(size_t)s*EENC], acc);
    cpart[sq][el] = acc;
    __syncthreads();
    if (tid < 64){
        float ctx = cpart[0][tid]+cpart[1][tid]+cpart[2][tid]+cpart[3][tid];
        g_xcat0[b*K0 + 256 + e] = ctx;
        g_Xall[((size_t)(b*TT+t))*KL + 512 + e] = tf32r(ctx);
    }
}

// gates split-K via tf32 MMA with hi/lo compensation:
// partial[chunk][32][2048] += Xhi@Whi^T + Xhi@Wlo^T + Xlo@Whi^T over 128-wide K chunk
// grid (16 n-tiles of 128, KC chunks); 256 threads = 8 warps; warp tile m32 x n16
__global__ __launch_bounds__(256) void gates_mma(
    const float* __restrict__ X, const float* __restrict__ Whi,
    const float* __restrict__ Wlo, float* __restrict__ Cp, int K)
{
    __shared__ __align__(16) float Xh[32][36], Xl[32][36];
    __shared__ __align__(16) float Bh[128][36], Bl[128][36];
    const int tid = threadIdx.x, lane = tid&31, w = tid>>5;
    const int lr = lane>>2, lc = lane&3;
    const int j0 = blockIdx.x*128;
    const int k0 = blockIdx.y*128;
    float d[2][2][4] = {};

    for (int kt = 0; kt < 4; ++kt){
        const int kk = k0 + kt*32;
        {   // stage X 32x32: one float4 per thread, split hi/lo
            int r = tid>>3, c = (tid&7)*4;
            float4 xv = *reinterpret_cast<const float4*>(X + (size_t)r*K + kk + c);
            float4 hi, lo;
            hi.x=tf32r(xv.x); lo.x=tf32r(xv.x-hi.x);
            hi.y=tf32r(xv.y); lo.y=tf32r(xv.y-hi.y);
            hi.z=tf32r(xv.z); lo.z=tf32r(xv.z-hi.z);
            hi.w=tf32r(xv.w); lo.w=tf32r(xv.w-hi.w);
            *reinterpret_cast<float4*>(&Xh[r][c]) = hi;
            *reinterpret_cast<float4*>(&Xl[r][c]) = lo;
        }
#pragma unroll
        for (int i=0;i<4;i++){  // stage W 128x32 hi+lo
            int f = tid + i*256;
            int r = f>>3, c = (f&7)*4;
            *reinterpret_cast<float4*>(&Bh[r][c]) =
                *reinterpret_cast<const float4*>(Whi + (size_t)(j0+r)*K + kk + c);
            *reinterpret_cast<float4*>(&Bl[r][c]) =
                *reinterpret_cast<const float4*>(Wlo + (size_t)(j0+r)*K + kk + c);
        }
        __syncthreads();
#pragma unroll
        for (int k8=0;k8<4;k8++){
            const int co = k8*8;
            unsigned ah[2][4], al[2][4];
#pragma unroll
            for (int mi=0;mi<2;mi++){
                int rb = mi*16 + lr;
                ah[mi][0]=__float_as_uint(Xh[rb  ][co+lc]);
                ah[mi][1]=__float_as_uint(Xh[rb+8][co+lc]);
                ah[mi][2]=__float_as_uint(Xh[rb  ][co+lc+4]);
                ah[mi][3]=__float_as_uint(Xh[rb+8][co+lc+4]);
                al[mi][0]=__float_as_uint(Xl[rb  ][co+lc]);
                al[mi][1]=__float_as_uint(Xl[rb+8][co+lc]);
                al[mi][2]=__float_as_uint(Xl[rb  ][co+lc+4]);
                al[mi][3]=__float_as_uint(Xl[rb+8][co+lc+4]);
            }
#pragma unroll
            for (int nj=0;nj<2;nj++){
                int nb = w*16 + nj*8 + lr;
                unsigned bh0 = __float_as_uint(Bh[nb][co+lc]);
                unsigned bh1 = __float_as_uint(Bh[nb][co+lc+4]);
                unsigned bl0 = __float_as_uint(Bl[nb][co+lc]);
                unsigned bl1 = __float_as_uint(Bl[nb][co+lc+4]);
#pragma unroll
                for (int mi=0;mi<2;mi++){
#define GMMA(AA,B0,B1) asm volatile( \
    "mma.sync.aligned.m16n8k8.row.col.f32.tf32.tf32.f32 " \
    "{%0,%1,%2,%3},{%4,%5,%6,%7},{%8,%9},{%0,%1,%2,%3};" \
    : "+f"(d[mi][nj][0]),"+f"(d[mi][nj][1]),"+f"(d[mi][nj][2]),"+f"(d[mi][nj][3]) \
    : "r"(AA[mi][0]),"r"(AA[mi][1]),"r"(AA[mi][2]),"r"(AA[mi][3]),"r"(B0),"r"(B1))
                    GMMA(ah, bh0, bh1);
                    GMMA(ah, bl0, bl1);
                    GMMA(al, bh0, bh1);
#undef GMMA
                }
            }
        }
        __syncthreads();
    }
    float* out = Cp + blockIdx.y*65536;
#pragma unroll
    for (int mi=0;mi<2;mi++){
#pragma unroll
        for (int nj=0;nj<2;nj++){
            int col = j0 + w*16 + nj*8 + lc*2;
            int m  = mi*16 + lr;
            *reinterpret_cast<float2*>(&out[(size_t)m*2048 + col])     = make_float2(d[mi][nj][0], d[mi][nj][1]);
            *reinterpret_cast<float2*>(&out[(size_t)(m+8)*2048 + col]) = make_float2(d[mi][nj][2], d[mi][nj][3]);
        }
    }
}

__global__ __launch_bounds__(512) void cell0_kernel()
{
    const int b = blockIdx.x, u = threadIdx.x;
    float gi=g_bcat0[u], gf=g_bcat0[512+u], gg=g_bcat0[1024+u], go=g_bcat0[1536+u];
#pragma unroll
    for (int s=0;s<10;s++){
        const float* p = g_part0 + s*65536 + b*2048;
        gi += p[u]; gf += p[512+u]; gg += p[1024+u]; go += p[1536+u];
    }
    float c = sigf(gf)*g_c0[b*HH+u] + sigf(gi)*tanh_acc(gg);
    float h = sigf(go)*tanh_acc(c);
    g_c0[b*HH+u] = c;
    g_xcat0[b*K0 + 768 + u] = h;
    g_xcat1[b*K1 + u]       = h;
}

__global__ __launch_bounds__(512) void cell1_kernel(const float* __restrict__ bq, int t)
{
    const int b = blockIdx.x, u = threadIdx.x;
    __shared__ __align__(16) float h1s[512];
    __shared__ __align__(16) float qpart[4][512];
    float gi=g_bcat1[u], gf=g_bcat1[512+u], gg=g_bcat1[1024+u], go=g_bcat1[1536+u];
#pragma unroll
    for (int s=0;s<8;s++){
        const float* p = g_part1 + s*65536 + b*2048;
        gi += p[u]; gf += p[512+u]; gg += p[1024+u]; go += p[1536+u];
    }
    float c = sigf(gf)*g_c1[b*HH+u] + sigf(gi)*tanh_acc(gg);
    float h = sigf(go)*tanh_acc(c);
    g_c1[b*HH+u] = c;
    g_h1[b*HH+u] = h;
    g_xcat1[b*K1 + 512 + u] = h;
    g_Xall[((size_t)(b*TT+t))*KL + u] = tf32r(h);
    h1s[u] = h;
    __syncthreads();
    const int h4 = (u & 127)*4, kp = u >> 7;
    float4 a = make_float4(0.f,0.f,0.f,0.f);
    const float* wb = g_Wqt + (size_t)kp*128*HH + h4;
#pragma unroll 4
    for (int k=0;k<128;k++){
        float4 w4 = *reinterpret_cast<const float4*>(wb + (size_t)k*HH);
        float xv = h1s[kp*128 + k];
        a.x=fmaf(w4.x,xv,a.x); a.y=fmaf(w4.y,xv,a.y);
        a.z=fmaf(w4.z,xv,a.z); a.w=fmaf(w4.w,xv,a.w);
    }
    *reinterpret_cast<float4*>(&qpart[kp][h4]) = a;
    __syncthreads();
    g_qp[b*HH+u] = qpart[0][u]+qpart[1][u]+qpart[2][u]+qpart[3][u] + bq[u];
}

// logits: tf32 mma.sync, BM128 x BN128 x BK16, 8 warps; grid (M/128, N/128) m-major
__global__ __launch_bounds__(256) void logits_mma(
    const float* __restrict__ A, const float* __restrict__ B,
    const float* __restrict__ bias, float* __restrict__ C)
{
    __shared__ __align__(16) float As[2][128][20];
    __shared__ __align__(16) float Bs[2][128][20];
    const int tid = threadIdx.x, lane = tid&31, w = tid>>5;
    const int wm = (w&3)*32, wn = (w>>2)*64;
    const int m0 = blockIdx.x*128, n0 = blockIdx.y*128;
    const int lr = lane>>2, lc = lane&3;
    float d[2][8][4] = {};

#define STAGE(bufi, kt) do { \
    int kk = (kt)*16; \
    _Pragma("unroll") \
    for (int i=0;i<2;i++){ \
        int f = tid + i*256; int r = f>>2, c = f&3; \
        unsigned dst = (unsigned)__cvta_generic_to_shared(&As[bufi][r][c*4]); \
        const float* src = A + (size_t)(m0+r)*KL + kk + c*4; \
        asm volatile("cp.async.cg.shared.global [%0], [%1], 16;"::"r"(dst),"l"(src)); \
    } \
    _Pragma("unroll") \
    for (int i=0;i<2;i++){ \
        int f = tid + i*256; int r = f>>2, c = f&3; \
        unsigned dst = (unsigned)__cvta_generic_to_shared(&Bs[bufi][r][c*4]); \
        const float* src = B + (size_t)(n0+r)*KL + kk + c*4; \
        asm volatile("cp.async.cg.shared.global [%0], [%1], 16;"::"r"(dst),"l"(src)); \
    } \
    asm volatile("cp.async.commit_group;"); \
} while(0)

    STAGE(0, 0);
    const int KT = KL/16;
    for (int kt=0; kt<KT; ++kt){
        const int buf = kt&1;
        if (kt+1 < KT){ STAGE(buf^1, kt+1); asm volatile("cp.async.wait_group 1;"); }
        else          { asm volatile("cp.async.wait_group 0;"); }
        __syncthreads();
#pragma unroll
        for (int k8=0;k8<2;k8++){
            const int co = k8*8;
            unsigned a[2][4];
#pragma unroll
            for (int mi=0;mi<2;mi++){
                int rb = wm + mi*16 + lr;
                a[mi][0] = __float_as_uint(As[buf][rb  ][co+lc]);
                a[mi][1] = __float_as_uint(As[buf][rb+8][co+lc]);
                a[mi][2] = __float_as_uint(As[buf][rb  ][co+lc+4]);
                a[mi][3] = __float_as_uint(As[buf][rb+8][co+lc+4]);
            }
#pragma unroll
            for (int nj=0;nj<8;nj++){
                int nb = wn + nj*8 + lr;
                unsigned b0 = __float_as_uint(Bs[buf][nb][co+lc]);
                unsigned b1 = __float_as_uint(Bs[buf][nb][co+lc+4]);
#pragma unroll
                for (int mi=0;mi<2;mi++){
                    asm volatile(
                      "mma.sync.aligned.m16n8k8.row.col.f32.tf32.tf32.f32 "
                      "{%0,%1,%2,%3},{%4,%5,%6,%7},{%8,%9},{%0,%1,%2,%3};"
                      : "+f"(d[mi][nj][0]),"+f"(d[mi][nj][1]),"+f"(d[mi][nj][2]),"+f"(d[mi][nj][3])
                      : "r"(a[mi][0]),"r"(a[mi][1]),"r"(a[mi][2]),"r"(a[mi][3]),"r"(b0),"r"(b1));
                }
            }
        }
        __syncthreads();
    }
#undef STAGE

    float* ep = &As[0][0][0] + w*640;
#pragma unroll
    for (int h=0; h<4; h++){
#pragma unroll
        for (int mi=0;mi<2;mi++){
#pragma unroll
            for (int njl=0;njl<2;njl++){
                int nj = h*2 + njl;
                int r0 = mi*16 + lr;
                ep[ r0   *20 + njl*8 + lc*2    ] = d[mi][nj][0];
                ep[ r0   *20 + njl*8 + lc*2 + 1] = d[mi][nj][1];
                ep[(r0+8)*20 + njl*8 + lc*2    ] = d[mi][nj][2];
                ep[(r0+8)*20 + njl*8 + lc*2 + 1] = d[mi][nj][3];
            }
        }
        __syncwarp();
#pragma unroll
        for (int q=0;q<4;q++){
            int idx = q*32 + lane;
            int r = idx>>2, c4 = idx&3;
            float4 vv = *reinterpret_cast<float4*>(&ep[r*20 + c4*4]);
            size_t nn = (size_t)n0 + wn + h*16 + c4*4;
            float4 bb = *reinterpret_cast<const float4*>(&bias[nn]);
            vv.x+=bb.x; vv.y+=bb.y; vv.z+=bb.z; vv.w+=bb.w;
            *reinterpret_cast<float4*>(&C[(size_t)(m0+wm+r)*VV + nn]) = vv;
        }
        __syncwarp();
    }
}

__global__ __launch_bounds__(512) void tail_kernel(float* __restrict__ out)
{
    int idx = blockIdx.x*blockDim.x + threadIdx.x;
    int part = idx / (BB*HH);
    int off  = idx % (BB*HH);
    int b = off / HH, u = off % HH;
    float val;
    if      (part == 0) val = g_xcat1[b*K1 + u];
    else if (part == 1) val = g_h1[off];
    else if (part == 2) val = g_c0[off];
    else                val = g_c1[off];
    out[OUT_TAIL_OFF + idx] = val;
}

extern "C" void kernel_launch(void* const* d_in, const int* in_sizes, int n_in,
                              void* d_out, int out_size)
{
    const float* enc  = (const float*)d_in[0];
    const int*   tok  = (const int*)  d_in[1];
    const float* emb  = (const float*)d_in[2];
    const float* Wq   = (const float*)d_in[3];
    const float* bq   = (const float*)d_in[4];
    const float* Wk   = (const float*)d_in[5];
    const float* bk   = (const float*)d_in[6];
    const float* v    = (const float*)d_in[7];
    const float* Wih0 = (const float*)d_in[8];
    const float* Whh0 = (const float*)d_in[9];
    const float* bih0 = (const float*)d_in[10];
    const float* bhh0 = (const float*)d_in[11];
    const float* Wih1 = (const float*)d_in[12];
    const float* Whh1 = (const float*)d_in[13];
    const float* bih1 = (const float*)d_in[14];
    const float* bhh1 = (const float*)d_in[15];
    const float* Wout = (const float*)d_in[16];
    const float* bout = (const float*)d_in[17];
    float* out = (float*)d_out;

    float *p_keyproj, *p_W0hi, *p_W0lo, *p_W1hi, *p_W1lo, *p_Wt32;
    float *p_xcat0, *p_xcat1, *p_part0, *p_part1, *p_Xall;
    cudaGetSymbolAddress((void**)&p_keyproj, g_keyproj);
    cudaGetSymbolAddress((void**)&p_W0hi,  g_W0hi);
    cudaGetSymbolAddress((void**)&p_W0lo,  g_W0lo);
    cudaGetSymbolAddress((void**)&p_W1hi,  g_W1hi);
    cudaGetSymbolAddress((void**)&p_W1lo,  g_W1lo);
    cudaGetSymbolAddress((void**)&p_Wt32,  g_Wt32);
    cudaGetSymbolAddress((void**)&p_xcat0, g_xcat0);
    cudaGetSymbolAddress((void**)&p_xcat1, g_xcat1);
    cudaGetSymbolAddress((void**)&p_part0, g_part0);
    cudaGetSymbolAddress((void**)&p_part1, g_part1);
    cudaGetSymbolAddress((void**)&p_Xall,  g_Xall);

    init_kernel<<<2048, 256>>>(Wih0, Whh0, bih0, bhh0, Wih1, Whh1, bih1, bhh1, Wq, bq);
    cvt_wout<<<2048, 256>>>(Wout);

    {   // key_proj = enc(8192x512) @ Wk^T + bk, then convert to fp16
        dim3 grid(HH/64, (BB*SS)/64);
        gemm_tn<64,64,16,4,4,256><<<grid, 256>>>(enc, Wk, bk, p_keyproj, BB*SS, HH, EENC);
        cvt_kp<<<2048, 256>>>();
    }

    for (int t = 0; t < TT; ++t){
        scores_kernel<<<dim3(BB, 32), 256>>>(v);
        smctx_kernel<<<dim3(BB, 8), 256>>>(enc, tok, emb, t);
        gates_mma<<<dim3(16, 10), 256>>>(p_xcat0, p_W0hi, p_W0lo, p_part0, K0);
        cell0_kernel<<<BB, 512>>>();
        gates_mma<<<dim3(16, 8), 256>>>(p_xcat1, p_W1hi, p_W1lo, p_part1, K1);
        cell1_kernel<<<BB, 512>>>(bq, t);
    }

    {   // logits = Xall(4096x1024) @ Wt32^T + bout  (m-major grid for B-tile reuse)
        dim3 grid((BB*TT)/128, VV/128);
        logits_mma<<<grid, 256>>>(p_Xall, p_Wt32, bout, out);
    }
    tail_kernel<<<128, 512>>>(out);
}

// round 15
// speedup vs baseline: 1.4055x; 1.0814x over previous
#include <cuda_runtime.h>
#include <cuda_fp16.h>
#include <cstdint>

#define BB 32
#define SS 256
#define TT 128
#define EENC 512
#define HH 512
#define EEMB 256
#define VV 32000
#define K0 1280
#define K1 1024
#define KL 1024
#define OUT_TAIL_OFF 131072000ll

__device__ float  g_keyproj[BB*SS*HH];
__device__ __half g_kph[BB*SS*HH];
__device__ __half g_ench[BB*SS*EENC];
__device__ float g_W0hi[2048*K0];
__device__ float g_W0lo[2048*K0];
__device__ float g_W1hi[2048*K1];
__device__ float g_W1lo[2048*K1];
__device__ float g_bcat0[2048];
__device__ float g_bcat1[2048];
__device__ float g_Wqt[HH*HH];
__device__ float g_Wt32[(size_t)VV*KL];
__device__ float g_xcat0[BB*K0];   // [emb | ctx | h0]
__device__ float g_xcat1[BB*K1];   // [h0 | h1]
__device__ float g_part0[10*BB*2048];
__device__ float g_part1[8*BB*2048];
__device__ float g_h1[BB*HH];
__device__ float g_c0[BB*HH];
__device__ float g_c1[BB*HH];
__device__ float g_qp[BB*HH];
__device__ float g_scores[BB*SS];
__device__ float g_Xall[(size_t)BB*TT*KL];

__device__ __forceinline__ float tanh_acc(float x){
    float xx = fminf(15.f, fmaxf(-15.f, x));
    float e  = __expf(2.f*xx);
    return 1.f - __fdividef(2.f, e + 1.f);
}
__device__ __forceinline__ float sigf(float x){
    float xx = fminf(30.f, fmaxf(-30.f, x));
    return __fdividef(1.f, 1.f + __expf(-xx));
}
__device__ __forceinline__ float tanh_fast(float x){
    float y; asm("tanh.approx.f32 %0, %1;" : "=f"(y) : "f"(x));
    return y;
}
__device__ __forceinline__ float tf32r(float x){
    unsigned u; asm("cvt.rna.tf32.f32 %0, %1;" : "=r"(u) : "f"(x));
    return __uint_as_float(u);
}

__global__ void init_kernel(const float* __restrict__ Wih0, const float* __restrict__ Whh0,
                            const float* __restrict__ bih0, const float* __restrict__ bhh0,
                            const float* __restrict__ Wih1, const float* __restrict__ Whh1,
                            const float* __restrict__ bih1, const float* __restrict__ bhh1,
                            const float* __restrict__ Wq,   const float* __restrict__ bq)
{
    const int NW0=2048*K0, NW1=2048*K1, NB=2048, NWQ=HH*HH, NQP=BB*HH;
    const int NZ = BB*HH*3 + BB*K0 + BB*K1;
    const int TOT = NW0+NW1+2*NB+NWQ+NQP+NZ;
    for (int idx = blockIdx.x*blockDim.x+threadIdx.x; idx < TOT; idx += gridDim.x*blockDim.x){
        int r = idx;
        if (r < NW0){
            int j=r/K0,k=r%K0;
            float w = (k<768) ? Wih0[j*768+k] : Whh0[j*512+(k-768)];
            float hi = tf32r(w);
            g_W0hi[r] = hi;
            g_W0lo[r] = tf32r(w - hi);
            continue;
        }
        r -= NW0;
        if (r < NW1){
            int j=r/K1,k=r%K1;
            float w = (k<512) ? Wih1[j*512+k] : Whh1[j*512+(k-512)];
            float hi = tf32r(w);
            g_W1hi[r] = hi;
            g_W1lo[r] = tf32r(w - hi);
            continue;
        }
        r -= NW1;
        if (r < NB){ g_bcat0[r]=bih0[r]+bhh0[r]; continue; }
        r -= NB;
        if (r < NB){ g_bcat1[r]=bih1[r]+bhh1[r]; continue; }
        r -= NB;
        if (r < NWQ){ int k=r/HH,h=r%HH; g_Wqt[r]=Wq[h*HH+k]; continue; }
        r -= NWQ;
        if (r < NQP){ g_qp[r]=bq[r%HH]; continue; }
        r -= NQP;
        if (r < BB*HH){ g_h1[r]=0.f; continue; }
        r -= BB*HH;
        if (r < BB*HH){ g_c0[r]=0.f; continue; }
        r -= BB*HH;
        if (r < BB*HH){ g_c1[r]=0.f; continue; }
        r -= BB*HH;
        if (r < BB*K0){ g_xcat0[r]=0.f; continue; }
        r -= BB*K0;
        g_xcat1[r]=0.f;
    }
}

__global__ void cvt_wout(const float* __restrict__ Wout)
{
    size_t n = (size_t)VV*KL/4;
    for (size_t i = blockIdx.x*blockDim.x+threadIdx.x; i < n; i += (size_t)gridDim.x*blockDim.x){
        float4 v = reinterpret_cast<const float4*>(Wout)[i];
        v.x=tf32r(v.x); v.y=tf32r(v.y); v.z=tf32r(v.z); v.w=tf32r(v.w);
        reinterpret_cast<float4*>(g_Wt32)[i] = v;
    }
}

// one-time fp32->fp16 conversions: keyproj and enc
__global__ void cvt_kp()
{
    int n = BB*SS*HH/2;
    for (int i = blockIdx.x*blockDim.x+threadIdx.x; i < n; i += gridDim.x*blockDim.x){
        float2 f = reinterpret_cast<const float2*>(g_keyproj)[i];
        reinterpret_cast<__half2*>(g_kph)[i] = __floats2half2_rn(f.x, f.y);
    }
}
__global__ void cvt_enc(const float* __restrict__ enc)
{
    int n = BB*SS*EENC/2;
    for (int i = blockIdx.x*blockDim.x+threadIdx.x; i < n; i += gridDim.x*blockDim.x){
        float2 f = reinterpret_cast<const float2*>(enc)[i];
        reinterpret_cast<__half2*>(g_ench)[i] = __floats2half2_rn(f.x, f.y);
    }
}

// fp32 GEMM for keyproj: C = A@B^T + bias
template<int BM,int BN,int BK,int TM,int TN,int THREADS>
__global__ __launch_bounds__(THREADS) void gemm_tn(
    const float* __restrict__ A, const float* __restrict__ B,
    const float* __restrict__ bias, float* __restrict__ C, int M, int N, int K)
{
    constexpr int AF4 = BM*BK/(4*THREADS);
    constexpr int BF4 = BN*BK/(4*THREADS);
    constexpr int KC4 = BK/4;
    constexpr int NT  = BN/TN;
    __shared__ __align__(16) float As[2][BK][BM];
    __shared__ __align__(16) float Bs[2][BK][BN];
    const int tid = threadIdx.x;
    const int tm = (tid/NT)*TM, tn = (tid%NT)*TN;
    const size_t m0 = (size_t)blockIdx.y*BM, n0 = (size_t)blockIdx.x*BN;
    const float* Ab = A + m0*K;
    const float* Bb = B + n0*K;
    float acc[TM][TN];
#pragma unroll
    for (int i=0;i<TM;i++)
#pragma unroll
        for (int j=0;j<TN;j++) acc[i][j]=0.f;
    float4 ra[AF4], rb[BF4];
#pragma unroll
    for (int i=0;i<AF4;i++){ int f=tid+i*THREADS,r=f/KC4,c=f%KC4;
        ra[i]=*reinterpret_cast<const float4*>(Ab+(size_t)r*K+c*4); }
#pragma unroll
    for (int i=0;i<BF4;i++){ int f=tid+i*THREADS,r=f/KC4,c=f%KC4;
        rb[i]=*reinterpret_cast<const float4*>(Bb+(size_t)r*K+c*4); }
#pragma unroll
    for (int i=0;i<AF4;i++){ int f=tid+i*THREADS,r=f/KC4,c=f%KC4;
        As[0][c*4+0][r]=ra[i].x; As[0][c*4+1][r]=ra[i].y; As[0][c*4+2][r]=ra[i].z; As[0][c*4+3][r]=ra[i].w; }
#pragma unroll
    for (int i=0;i<BF4;i++){ int f=tid+i*THREADS,r=f/KC4,c=f%KC4;
        Bs[0][c*4+0][r]=rb[i].x; Bs[0][c*4+1][r]=rb[i].y; Bs[0][c*4+2][r]=rb[i].z; Bs[0][c*4+3][r]=rb[i].w; }
    __syncthreads();
    const int KT = K/BK;
    for (int kt=0; kt<KT; ++kt){
        const int cur = kt&1;
        const bool nx = (kt+1<KT);
        if (nx){
            const float* A2 = Ab+(size_t)(kt+1)*BK;
            const float* B2 = Bb+(size_t)(kt+1)*BK;
#pragma unroll
            for (int i=0;i<AF4;i++){ int f=tid+i*THREADS,r=f/KC4,c=f%KC4;
                ra[i]=*reinterpret_cast<const float4*>(A2+(size_t)r*K+c*4); }
#pragma unroll
            for (int i=0;i<BF4;i++){ int f=tid+i*THREADS,r=f/KC4,c=f%KC4;
                rb[i]=*reinterpret_cast<const float4*>(B2+(size_t)r*K+c*4); }
        }
#pragma unroll
        for (int k=0;k<BK;k++){
            float a[TM], b[TN];
#pragma unroll
            for (int i=0;i<TM/4;i++){ float4 t=*reinterpret_cast<const float4*>(&As[cur][k][tm+i*4]);
                a[i*4]=t.x;a[i*4+1]=t.y;a[i*4+2]=t.z;a[i*4+3]=t.w; }
#pragma unroll
            for (int j=0;j<TN/4;j++){ float4 t=*reinterpret_cast<const float4*>(&Bs[cur][k][tn+j*4]);
                b[j*4]=t.x;b[j*4+1]=t.y;b[j*4+2]=t.z;b[j*4+3]=t.w; }
#pragma unroll
            for (int i=0;i<TM;i++)
#pragma unroll
                for (int j=0;j<TN;j++) acc[i][j]=fmaf(a[i],b[j],acc[i][j]);
        }
        if (nx){
            const int nb = cur^1;
#pragma unroll
            for (int i=0;i<AF4;i++){ int f=tid+i*THREADS,r=f/KC4,c=f%KC4;
                As[nb][c*4+0][r]=ra[i].x; As[nb][c*4+1][r]=ra[i].y; As[nb][c*4+2][r]=ra[i].z; As[nb][c*4+3][r]=ra[i].w; }
#pragma unroll
            for (int i=0;i<BF4;i++){ int f=tid+i*THREADS,r=f/KC4,c=f%KC4;
                Bs[nb][c*4+0][r]=rb[i].x; Bs[nb][c*4+1][r]=rb[i].y; Bs[nb][c*4+2][r]=rb[i].z; Bs[nb][c*4+3][r]=rb[i].w; }
            __syncthreads();
        }
    }
#pragma unroll
    for (int i=0;i<TM;i++)
#pragma unroll
        for (int j=0;j<TN;j++){
            size_t cn = n0+tn+j;
            C[(m0+tm+i)*(size_t)N+cn] = acc[i][j] + bias[cn];
        }
}

// scores: one warp per (b, s); grid (32, 32); keyproj read as fp16
__global__ __launch_bounds__(256) void scores_kernel(const float* __restrict__ v)
{
    const int b = blockIdx.x, tid = threadIdx.x;
    const int w = tid>>5, lane = tid&31;
    __shared__ __align__(16) float qs[512], vsm[512];
    qs[tid]      = g_qp[b*HH+tid];
    qs[tid+256]  = g_qp[b*HH+tid+256];
    vsm[tid]     = v[tid];
    vsm[tid+256] = v[tid+256];
    __syncthreads();
    const int s = blockIdx.y*8 + w;
    const __half* kp = g_kph + ((size_t)(b*SS+s))*HH;
    float acc = 0.f;
#pragma unroll
    for (int i=0;i<4;i++){
        int h = i*128 + lane*4;
        uint2 kk = *reinterpret_cast<const uint2*>(kp + h);
        float2 f01 = __half22float2(*reinterpret_cast<const __half2*>(&kk.x));
        float2 f23 = __half22float2(*reinterpret_cast<const __half2*>(&kk.y));
        float4 q4 = *reinterpret_cast<const float4*>(&qs[h]);
        float4 v4 = *reinterpret_cast<const float4*>(&vsm[h]);
        acc = fmaf(v4.x, tanh_fast(f01.x+q4.x), acc);
        acc = fmaf(v4.y, tanh_fast(f01.y+q4.y), acc);
        acc = fmaf(v4.z, tanh_fast(f23.x+q4.z), acc);
        acc = fmaf(v4.w, tanh_fast(f23.y+q4.w), acc);
    }
#pragma unroll
    for (int o=16;o;o>>=1) acc += __shfl_xor_sync(0xffffffffu, acc, o);
    if (lane == 0) g_scores[b*SS+s] = acc;
}

// softmax + 64-col context chunk (enc as fp16) + emb gather; grid (32, 8)
__global__ __launch_bounds__(256) void smctx_kernel(
    const int* __restrict__ tok, const float* __restrict__ emb, int t)
{
    const int b = blockIdx.x, chunk = blockIdx.y, tid = threadIdx.x;
    const int w = tid>>5, lane = tid&31;
    __shared__ __align__(16) float wsm[SS];
    __shared__ __align__(16) float cpart[4][64];
    __shared__ float red[8];
    __shared__ float smax_s, sinv_s;
    float x = g_scores[b*SS+tid];
    float m = x;
#pragma unroll
    for (int o=16;o;o>>=1) m = fmaxf(m, __shfl_xor_sync(0xffffffffu, m, o));
    if (lane==0) red[w]=m;
    __syncthreads();
    if (tid==0){ float mm=red[0];
#pragma unroll
        for (int i=1;i<8;i++) mm=fmaxf(mm,red[i]); smax_s=mm; }
    __syncthreads();
    float ex = __expf(x - smax_s);
    float s2 = ex;
#pragma unroll
    for (int o=16;o;o>>=1) s2 += __shfl_xor_sync(0xffffffffu, s2, o);
    if (lane==0) red[w]=s2;
    __syncthreads();
    if (tid==0){ float ss=0.f;
#pragma unroll
        for (int i=0;i<8;i++) ss+=red[i]; sinv_s=1.f/ss; }
    __syncthreads();
    wsm[tid] = ex*sinv_s;
    if (chunk == 0){
        int row = tok[b*TT+t];
        g_xcat0[b*K0+tid] = emb[(size_t)row*EEMB+tid];
    }
    __syncthreads();
    const int el = tid & 63, sq = tid >> 6;
    const int e = chunk*64 + el;
    const __half* eb = g_ench + ((size_t)(b*SS) + sq*64)*EENC + e;
    float acc = 0.f;
#pragma unroll 4
    for (int s=0;s<64;s++) acc = fmaf(wsm[sq*64+s], __half2float(eb[(size_t)s*EENC]), acc);
    cpart[sq][el] = acc;
    __syncthreads();
    if (tid < 64){
        float ctx = cpart[0][tid]+cpart[1][tid]+cpart[2][tid]+cpart[3][tid];
        g_xcat0[b*K0 + 256 + e] = ctx;
        g_Xall[((size_t)(b*TT+t))*KL + 512 + e] = tf32r(ctx);
    }
}

// gates split-K via tf32 MMA with hi/lo compensation (unchanged from passing R14)
__global__ __launch_bounds__(256) void gates_mma(
    const float* __restrict__ X, const float* __restrict__ Whi,
    const float* __restrict__ Wlo, float* __restrict__ Cp, int K)
{
    __shared__ __align__(16) float Xh[32][36], Xl[32][36];
    __shared__ __align__(16) float Bh[128][36], Bl[128][36];
    const int tid = threadIdx.x, lane = tid&31, w = tid>>5;
    const int lr = lane>>2, lc = lane&3;
    const int j0 = blockIdx.x*128;
    const int k0 = blockIdx.y*128;
    float d[2][2][4] = {};

    for (int kt = 0; kt < 4; ++kt){
        const int kk = k0 + kt*32;
        {
            int r = tid>>3, c = (tid&7)*4;
            float4 xv = *reinterpret_cast<const float4*>(X + (size_t)r*K + kk + c);
            float4 hi, lo;
            hi.x=tf32r(xv.x); lo.x=tf32r(xv.x-hi.x);
            hi.y=tf32r(xv.y); lo.y=tf32r(xv.y-hi.y);
            hi.z=tf32r(xv.z); lo.z=tf32r(xv.z-hi.z);
            hi.w=tf32r(xv.w); lo.w=tf32r(xv.w-hi.w);
            *reinterpret_cast<float4*>(&Xh[r][c]) = hi;
            *reinterpret_cast<float4*>(&Xl[r][c]) = lo;
        }
#pragma unroll
        for (int i=0;i<4;i++){
            int f = tid + i*256;
            int r = f>>3, c = (f&7)*4;
            *reinterpret_cast<float4*>(&Bh[r][c]) =
                *reinterpret_cast<const float4*>(Whi + (size_t)(j0+r)*K + kk + c);
            *reinterpret_cast<float4*>(&Bl[r][c]) =
                *reinterpret_cast<const float4*>(Wlo + (size_t)(j0+r)*K + kk + c);
        }
        __syncthreads();
#pragma unroll
        for (int k8=0;k8<4;k8++){
            const int co = k8*8;
            unsigned ah[2][4], al[2][4];
#pragma unroll
            for (int mi=0;mi<2;mi++){
                int rb = mi*16 + lr;
                ah[mi][0]=__float_as_uint(Xh[rb  ][co+lc]);
                ah[mi][1]=__float_as_uint(Xh[rb+8][co+lc]);
                ah[mi][2]=__float_as_uint(Xh[rb  ][co+lc+4]);
                ah[mi][3]=__float_as_uint(Xh[rb+8][co+lc+4]);
                al[mi][0]=__float_as_uint(Xl[rb  ][co+lc]);
                al[mi][1]=__float_as_uint(Xl[rb+8][co+lc]);
                al[mi][2]=__float_as_uint(Xl[rb  ][co+lc+4]);
                al[mi][3]=__float_as_uint(Xl[rb+8][co+lc+4]);
            }
#pragma unroll
            for (int nj=0;nj<2;nj++){
                int nb = w*16 + nj*8 + lr;
                unsigned bh0 = __float_as_uint(Bh[nb][co+lc]);
                unsigned bh1 = __float_as_uint(Bh[nb][co+lc+4]);
                unsigned bl0 = __float_as_uint(Bl[nb][co+lc]);
                unsigned bl1 = __float_as_uint(Bl[nb][co+lc+4]);
#pragma unroll
                for (int mi=0;mi<2;mi++){
#define GMMA(AA,B0,B1) asm volatile( \
    "mma.sync.aligned.m16n8k8.row.col.f32.tf32.tf32.f32 " \
    "{%0,%1,%2,%3},{%4,%5,%6,%7},{%8,%9},{%0,%1,%2,%3};" \
    : "+f"(d[mi][nj][0]),"+f"(d[mi][nj][1]),"+f"(d[mi][nj][2]),"+f"(d[mi][nj][3]) \
    : "r"(AA[mi][0]),"r"(AA[mi][1]),"r"(AA[mi][2]),"r"(AA[mi][3]),"r"(B0),"r"(B1))
                    GMMA(ah, bh0, bh1);
                    GMMA(ah, bl0, bl1);
                    GMMA(al, bh0, bh1);
#undef GMMA
                }
            }
        }
        __syncthreads();
    }
    float* out = Cp + blockIdx.y*65536;
#pragma unroll
    for (int mi=0;mi<2;mi++){
#pragma unroll
        for (int nj=0;nj<2;nj++){
            int col = j0 + w*16 + nj*8 + lc*2;
            int m  = mi*16 + lr;
            *reinterpret_cast<float2*>(&out[(size_t)m*2048 + col])     = make_float2(d[mi][nj][0], d[mi][nj][1]);
            *reinterpret_cast<float2*>(&out[(size_t)(m+8)*2048 + col]) = make_float2(d[mi][nj][2], d[mi][nj][3]);
        }
    }
}

__global__ __launch_bounds__(512) void cell0_kernel()
{
    const int b = blockIdx.x, u = threadIdx.x;
    float gi=g_bcat0[u], gf=g_bcat0[512+u], gg=g_bcat0[1024+u], go=g_bcat0[1536+u];
#pragma unroll
    for (int s=0;s<10;s++){
        const float* p = g_part0 + s*65536 + b*2048;
        gi += p[u]; gf += p[512+u]; gg += p[1024+u]; go += p[1536+u];
    }
    float c = sigf(gf)*g_c0[b*HH+u] + sigf(gi)*tanh_acc(gg);
    float h = sigf(go)*tanh_acc(c);
    g_c0[b*HH+u] = c;
    g_xcat0[b*K0 + 768 + u] = h;
    g_xcat1[b*K1 + u]       = h;
}

__global__ __launch_bounds__(512) void cell1_kernel(const float* __restrict__ bq, int t)
{
    const int b = blockIdx.x, u = threadIdx.x;
    __shared__ __align__(16) float h1s[512];
    __shared__ __align__(16) float qpart[4][512];
    float gi=g_bcat1[u], gf=g_bcat1[512+u], gg=g_bcat1[1024+u], go=g_bcat1[1536+u];
#pragma unroll
    for (int s=0;s<8;s++){
        const float* p = g_part1 + s*65536 + b*2048;
        gi += p[u]; gf += p[512+u]; gg += p[1024+u]; go += p[1536+u];
    }
    float c = sigf(gf)*g_c1[b*HH+u] + sigf(gi)*tanh_acc(gg);
    float h = sigf(go)*tanh_acc(c);
    g_c1[b*HH+u] = c;
    g_h1[b*HH+u] = h;
    g_xcat1[b*K1 + 512 + u] = h;
    g_Xall[((size_t)(b*TT+t))*KL + u] = tf32r(h);
    h1s[u] = h;
    __syncthreads();
    const int h4 = (u & 127)*4, kp = u >> 7;
    float4 a = make_float4(0.f,0.f,0.f,0.f);
    const float* wb = g_Wqt + (size_t)kp*128*HH + h4;
#pragma unroll 4
    for (int k=0;k<128;k++){
        float4 w4 = *reinterpret_cast<const float4*>(wb + (size_t)k*HH);
        float xv = h1s[kp*128 + k];
        a.x=fmaf(w4.x,xv,a.x); a.y=fmaf(w4.y,xv,a.y);
        a.z=fmaf(w4.z,xv,a.z); a.w=fmaf(w4.w,xv,a.w);
    }
    *reinterpret_cast<float4*>(&qpart[kp][h4]) = a;
    __syncthreads();
    g_qp[b*HH+u] = qpart[0][u]+qpart[1][u]+qpart[2][u]+qpart[3][u] + bq[u];
}

// logits v3: tf32 mma, BM128 x BN128 x BK16, 3-stage cp.async (dynamic smem),
// ONE __syncthreads per 16-K; grid (M/128, N/128) m-major
__global__ __launch_bounds__(256) void logits_mma(
    const float* __restrict__ A, const float* __restrict__ B,
    const float* __restrict__ bias, float* __restrict__ C)
{
    extern __shared__ __align__(16) float smem_l[];
    float (*As)[128][20] = reinterpret_cast<float(*)[128][20]>(smem_l);
    float (*Bs)[128][20] = reinterpret_cast<float(*)[128][20]>(smem_l + 3*128*20);
    const int tid = threadIdx.x, lane = tid&31, w = tid>>5;
    const int wm = (w&3)*32, wn = (w>>2)*64;
    const int m0 = blockIdx.x*128, n0 = blockIdx.y*128;
    const int lr = lane>>2, lc = lane&3;
    float d[2][8][4] = {};

#define STAGE(bufi, kt) do { \
    int kk = (kt)*16; \
    _Pragma("unroll") \
    for (int i=0;i<2;i++){ \
        int f = tid + i*256; int r = f>>2, c = f&3; \
        unsigned dst = (unsigned)__cvta_generic_to_shared(&As[bufi][r][c*4]); \
        const float* src = A + (size_t)(m0+r)*KL + kk + c*4; \
        asm volatile("cp.async.cg.shared.global [%0], [%1], 16;"::"r"(dst),"l"(src)); \
    } \
    _Pragma("unroll") \
    for (int i=0;i<2;i++){ \
        int f = tid + i*256; int r = f>>2, c = f&3; \
        unsigned dst = (unsigned)__cvta_generic_to_shared(&Bs[bufi][r][c*4]); \
        const float* src = B + (size_t)(n0+r)*KL + kk + c*4; \
        asm volatile("cp.async.cg.shared.global [%0], [%1], 16;"::"r"(dst),"l"(src)); \
    } \
    asm volatile("cp.async.commit_group;"); \
} while(0)

    STAGE(0, 0);
    STAGE(1, 1);
    const int KT = KL/16;      // 64
    for (int kt=0; kt<KT; ++kt){
        const int buf = kt % 3;
        if (kt == KT-1) asm volatile("cp.async.wait_group 0;");
        else            asm volatile("cp.async.wait_group 1;");
        __syncthreads();
        if (kt+2 < KT) STAGE((kt+2)%3, kt+2);
#pragma unroll
        for (int k8=0;k8<2;k8++){
            const int co = k8*8;
            unsigned a[2][4];
#pragma unroll
            for (int mi=0;mi<2;mi++){
                int rb = wm + mi*16 + lr;
                a[mi][0] = __float_as_uint(As[buf][rb  ][co+lc]);
                a[mi][1] = __float_as_uint(As[buf][rb+8][co+lc]);
                a[mi][2] = __float_as_uint(As[buf][rb  ][co+lc+4]);
                a[mi][3] = __float_as_uint(As[buf][rb+8][co+lc+4]);
            }
#pragma unroll
            for (int nj=0;nj<8;nj++){
                int nb = wn + nj*8 + lr;
                unsigned b0 = __float_as_uint(Bs[buf][nb][co+lc]);
                unsigned b1 = __float_as_uint(Bs[buf][nb][co+lc+4]);
#pragma unroll
                for (int mi=0;mi<2;mi++){
                    asm volatile(
                      "mma.sync.aligned.m16n8k8.row.col.f32.tf32.tf32.f32 "
                      "{%0,%1,%2,%3},{%4,%5,%6,%7},{%8,%9},{%0,%1,%2,%3};"
                      : "+f"(d[mi][nj][0]),"+f"(d[mi][nj][1]),"+f"(d[mi][nj][2]),"+f"(d[mi][nj][3])
                      : "r"(a[mi][0]),"r"(a[mi][1]),"r"(a[mi][2]),"r"(a[mi][3]),"r"(b0),"r"(b1));
                }
            }
        }
    }
#undef STAGE
    __syncthreads();   // all warps done computing before reusing smem for epilogue

    float* ep = smem_l + w*640;
#pragma unroll
    for (int h=0; h<4; h++){
#pragma unroll
        for (int mi=0;mi<2;mi++){
#pragma unroll
            for (int njl=0;njl<2;njl++){
                int nj = h*2 + njl;
                int r0 = mi*16 + lr;
                ep[ r0   *20 + njl*8 + lc*2    ] = d[mi][nj][0];
                ep[ r0   *20 + njl*8 + lc*2 + 1] = d[mi][nj][1];
                ep[(r0+8)*20 + njl*8 + lc*2    ] = d[mi][nj][2];
                ep[(r0+8)*20 + njl*8 + lc*2 + 1] = d[mi][nj][3];
            }
        }
        __syncwarp();
#pragma unroll
        for (int q=0;q<4;q++){
            int idx = q*32 + lane;
            int r = idx>>2, c4 = idx&3;
            float4 vv = *reinterpret_cast<float4*>(&ep[r*20 + c4*4]);
            size_t nn = (size_t)n0 + wn + h*16 + c4*4;
            float4 bb = *reinterpret_cast<const float4*>(&bias[nn]);
            vv.x+=bb.x; vv.y+=bb.y; vv.z+=bb.z; vv.w+=bb.w;
            *reinterpret_cast<float4*>(&C[(size_t)(m0+wm+r)*VV + nn]) = vv;
        }
        __syncwarp();
    }
}

__global__ __launch_bounds__(512) void tail_kernel(float* __restrict__ out)
{
    int idx = blockIdx.x*blockDim.x + threadIdx.x;
    int part = idx / (BB*HH);
    int off  = idx % (BB*HH);
    int b = off / HH, u = off % HH;
    float val;
    if      (part == 0) val = g_xcat1[b*K1 + u];
    else if (part == 1) val = g_h1[off];
    else if (part == 2) val = g_c0[off];
    else                val = g_c1[off];
    out[OUT_TAIL_OFF + idx] = val;
}

extern "C" void kernel_launch(void* const* d_in, const int* in_sizes, int n_in,
                              void* d_out, int out_size)
{
    const float* enc  = (const float*)d_in[0];
    const int*   tok  = (const int*)  d_in[1];
    const float* emb  = (const float*)d_in[2];
    const float* Wq   = (const float*)d_in[3];
    const float* bq   = (const float*)d_in[4];
    const float* Wk   = (const float*)d_in[5];
    const float* bk   = (const float*)d_in[6];
    const float* v    = (const float*)d_in[7];
    const float* Wih0 = (const float*)d_in[8];
    const float* Whh0 = (const float*)d_in[9];
    const float* bih0 = (const float*)d_in[10];
    const float* bhh0 = (const float*)d_in[11];
    const float* Wih1 = (const float*)d_in[12];
    const float* Whh1 = (const float*)d_in[13];
    const float* bih1 = (const float*)d_in[14];
    const float* bhh1 = (const float*)d_in[15];
    const float* Wout = (const float*)d_in[16];
    const float* bout = (const float*)d_in[17];
    float* out = (float*)d_out;

    float *p_keyproj, *p_W0hi, *p_W0lo, *p_W1hi, *p_W1lo, *p_Wt32;
    float *p_xcat0, *p_xcat1, *p_part0, *p_part1, *p_Xall;
    cudaGetSymbolAddress((void**)&p_keyproj, g_keyproj);
    cudaGetSymbolAddress((void**)&p_W0hi,  g_W0hi);
    cudaGetSymbolAddress((void**)&p_W0lo,  g_W0lo);
    cudaGetSymbolAddress((void**)&p_W1hi,  g_W1hi);
    cudaGetSymbolAddress((void**)&p_W1lo,  g_W1lo);
    cudaGetSymbolAddress((void**)&p_Wt32,  g_Wt32);
    cudaGetSymbolAddress((void**)&p_xcat0, g_xcat0);
    cudaGetSymbolAddress((void**)&p_xcat1, g_xcat1);
    cudaGetSymbolAddress((void**)&p_part0, g_part0);
    cudaGetSymbolAddress((void**)&p_part1, g_part1);
    cudaGetSymbolAddress((void**)&p_Xall,  g_Xall);

    // opt-in 60KB dynamic smem for logits (host-side attribute; not an allocation)
    cudaFuncSetAttribute(logits_mma, cudaFuncAttributeMaxDynamicSharedMemorySize, 3*2*128*20*4);

    init_kernel<<<2048, 256>>>(Wih0, Whh0, bih0, bhh0, Wih1, Whh1, bih1, bhh1, Wq, bq);
    cvt_wout<<<2048, 256>>>(Wout);
    cvt_enc<<<2048, 256>>>(enc);

    {   // key_proj = enc(8192x512) @ Wk^T + bk, then convert to fp16
        dim3 grid(HH/64, (BB*SS)/64);
        gemm_tn<64,64,16,4,4,256><<<grid, 256>>>(enc, Wk, bk, p_keyproj, BB*SS, HH, EENC);
        cvt_kp<<<2048, 256>>>();
    }

    for (int t = 0; t < TT; ++t){
        scores_kernel<<<dim3(BB, 32), 256>>>(v);
        smctx_kernel<<<dim3(BB, 8), 256>>>(tok, emb, t);
        gates_mma<<<dim3(16, 10), 256>>>(p_xcat0, p_W0hi, p_W0lo, p_part0, K0);
        cell0_kernel<<<BB, 512>>>();
        gates_mma<<<dim3(16, 8), 256>>>(p_xcat1, p_W1hi, p_W1lo, p_part1, K1);
        cell1_kernel<<<BB, 512>>>(bq, t);
    }

    {   // logits = Xall(4096x1024) @ Wt32^T + bout  (m-major grid for B-tile reuse)
        dim3 grid((BB*TT)/128, VV/128);
        logits_mma<<<grid, 256, 3*2*128*20*4>>>(p_Xall, p_Wt32, bout, out);
    }
    tail_kernel<<<128, 512>>>(out);
}

// round 16
// speedup vs baseline: 1.5269x; 1.0864x over previous
#include <cuda_runtime.h>
#include <cuda_fp16.h>
#include <cstdint>

#define BB 32
#define SS 256
#define TT 128
#define EENC 512
#define HH 512
#define EEMB 256
#define VV 32000
#define K0 1280
#define K1 1024
#define KL 1024
#define OUT_TAIL_OFF 131072000ll

__device__ __half g_kph[BB*SS*HH];
__device__ __half g_ench[BB*SS*EENC];
__device__ float g_W0hi[2048*K0];
__device__ float g_W0lo[2048*K0];
__device__ float g_W1hi[2048*K1];
__device__ float g_W1lo[2048*K1];
__device__ float g_bcat0[2048];
__device__ float g_bcat1[2048];
__device__ float g_Wqt[HH*HH];
__device__ float g_Wt32[(size_t)VV*KL];
__device__ float g_xcat0[BB*K0];   // [emb | ctx | h0]
__device__ float g_xcat1[BB*K1];   // [h0 | h1]
__device__ float g_part0[10*BB*2048];
__device__ float g_part1[8*BB*2048];
__device__ float g_h1[BB*HH];
__device__ float g_c0[BB*HH];
__device__ float g_c1[BB*HH];
__device__ float g_qp[BB*HH];
__device__ float g_scores[BB*SS];
__device__ float g_Xall[(size_t)BB*TT*KL];

__device__ __forceinline__ float tanh_acc(float x){
    float xx = fminf(15.f, fmaxf(-15.f, x));
    float e  = __expf(2.f*xx);
    return 1.f - __fdividef(2.f, e + 1.f);
}
__device__ __forceinline__ float sigf(float x){
    float xx = fminf(30.f, fmaxf(-30.f, x));
    return __fdividef(1.f, 1.f + __expf(-xx));
}
__device__ __forceinline__ float tanh_fast(float x){
    float y; asm("tanh.approx.f32 %0, %1;" : "=f"(y) : "f"(x));
    return y;
}
__device__ __forceinline__ float tf32r(float x){
    unsigned u; asm("cvt.rna.tf32.f32 %0, %1;" : "=r"(u) : "f"(x));
    return __uint_as_float(u);
}
// PDL: wait for predecessor kernel's results to be visible
__device__ __forceinline__ void gdep_wait(){
    asm volatile("griddepcontrol.wait;" ::: "memory");
}

__global__ void init_kernel(const float* __restrict__ Wih0, const float* __restrict__ Whh0,
                            const float* __restrict__ bih0, const float* __restrict__ bhh0,
                            const float* __restrict__ Wih1, const float* __restrict__ Whh1,
                            const float* __restrict__ bih1, const float* __restrict__ bhh1,
                            const float* __restrict__ Wq,   const float* __restrict__ bq)
{
    const int NW0=2048*K0, NW1=2048*K1, NB=2048, NWQ=HH*HH, NQP=BB*HH;
    const int NZ = BB*HH*3 + BB*K0 + BB*K1;
    const int TOT = NW0+NW1+2*NB+NWQ+NQP+NZ;
    for (int idx = blockIdx.x*blockDim.x+threadIdx.x; idx < TOT; idx += gridDim.x*blockDim.x){
        int r = idx;
        if (r < NW0){
            int j=r/K0,k=r%K0;
            float w = (k<768) ? Wih0[j*768+k] : Whh0[j*512+(k-768)];
            float hi = tf32r(w);
            g_W0hi[r] = hi;
            g_W0lo[r] = tf32r(w - hi);
            continue;
        }
        r -= NW0;
        if (r < NW1){
            int j=r/K1,k=r%K1;
            float w = (k<512) ? Wih1[j*512+k] : Whh1[j*512+(k-512)];
            float hi = tf32r(w);
            g_W1hi[r] = hi;
            g_W1lo[r] = tf32r(w - hi);
            continue;
        }
        r -= NW1;
        if (r < NB){ g_bcat0[r]=bih0[r]+bhh0[r]; continue; }
        r -= NB;
        if (r < NB){ g_bcat1[r]=bih1[r]+bhh1[r]; continue; }
        r -= NB;
        if (r < NWQ){ int k=r/HH,h=r%HH; g_Wqt[r]=Wq[h*HH+k]; continue; }
        r -= NWQ;
        if (r < NQP){ g_qp[r]=bq[r%HH]; continue; }
        r -= NQP;
        if (r < BB*HH){ g_h1[r]=0.f; continue; }
        r -= BB*HH;
        if (r < BB*HH){ g_c0[r]=0.f; continue; }
        r -= BB*HH;
        if (r < BB*HH){ g_c1[r]=0.f; continue; }
        r -= BB*HH;
        if (r < BB*K0){ g_xcat0[r]=0.f; continue; }
        r -= BB*K0;
        g_xcat1[r]=0.f;
    }
}

__global__ void cvt_wout(const float* __restrict__ Wout)
{
    size_t n = (size_t)VV*KL/4;
    for (size_t i = blockIdx.x*blockDim.x+threadIdx.x; i < n; i += (size_t)gridDim.x*blockDim.x){
        float4 v = reinterpret_cast<const float4*>(Wout)[i];
        v.x=tf32r(v.x); v.y=tf32r(v.y); v.z=tf32r(v.z); v.w=tf32r(v.w);
        reinterpret_cast<float4*>(g_Wt32)[i] = v;
    }
}

__global__ void cvt_enc(const float* __restrict__ enc)
{
    int n = BB*SS*EENC/2;
    for (int i = blockIdx.x*blockDim.x+threadIdx.x; i < n; i += gridDim.x*blockDim.x){
        float2 f = reinterpret_cast<const float2*>(enc)[i];
        reinterpret_cast<__half2*>(g_ench)[i] = __floats2half2_rn(f.x, f.y);
    }
}

// keyproj via tf32 MMA: g_kph[m][n] = fp16( enc(8192x512) @ Wk^T + bk )
// BM128 x BN128 x BK16, 2-stage; grid (64, 4)
__global__ __launch_bounds__(256) void keyproj_mma(
    const float* __restrict__ A, const float* __restrict__ B,
    const float* __restrict__ bias)
{
    __shared__ __align__(16) float As[2][128][20];
    __shared__ __align__(16) float Bs[2][128][20];
    const int tid = threadIdx.x, lane = tid&31, w = tid>>5;
    const int wm = (w&3)*32, wn = (w>>2)*64;
    const int m0 = blockIdx.x*128, n0 = blockIdx.y*128;
    const int lr = lane>>2, lc = lane&3;
    float d[2][8][4] = {};

#define KSTAGE(bufi, kt) do { \
    int kk = (kt)*16; \
    _Pragma("unroll") \
    for (int i=0;i<2;i++){ \
        int f = tid + i*256; int r = f>>2, c = f&3; \
        unsigned dst = (unsigned)__cvta_generic_to_shared(&As[bufi][r][c*4]); \
        const float* src = A + (size_t)(m0+r)*EENC + kk + c*4; \
        asm volatile("cp.async.cg.shared.global [%0], [%1], 16;"::"r"(dst),"l"(src)); \
    } \
    _Pragma("unroll") \
    for (int i=0;i<2;i++){ \
        int f = tid + i*256; int r = f>>2, c = f&3; \
        unsigned dst = (unsigned)__cvta_generic_to_shared(&Bs[bufi][r][c*4]); \
        const float* src = B + (size_t)(n0+r)*EENC + kk + c*4; \
        asm volatile("cp.async.cg.shared.global [%0], [%1], 16;"::"r"(dst),"l"(src)); \
    } \
    asm volatile("cp.async.commit_group;"); \
} while(0)

    KSTAGE(0, 0);
    const int KT = EENC/16;  // 32
    for (int kt=0; kt<KT; ++kt){
        const int buf = kt&1;
        if (kt+1 < KT){ KSTAGE(buf^1, kt+1); asm volatile("cp.async.wait_group 1;"); }
        else          { asm volatile("cp.async.wait_group 0;"); }
        __syncthreads();
#pragma unroll
        for (int k8=0;k8<2;k8++){
            const int co = k8*8;
            unsigned a[2][4];
#pragma unroll
            for (int mi=0;mi<2;mi++){
                int rb = wm + mi*16 + lr;
                a[mi][0] = __float_as_uint(tf32r(As[buf][rb  ][co+lc]));
                a[mi][1] = __float_as_uint(tf32r(As[buf][rb+8][co+lc]));
                a[mi][2] = __float_as_uint(tf32r(As[buf][rb  ][co+lc+4]));
                a[mi][3] = __float_as_uint(tf32r(As[buf][rb+8][co+lc+4]));
            }
#pragma unroll
            for (int nj=0;nj<8;nj++){
                int nb = wn + nj*8 + lr;
                unsigned b0 = __float_as_uint(tf32r(Bs[buf][nb][co+lc]));
                unsigned b1 = __float_as_uint(tf32r(Bs[buf][nb][co+lc+4]));
#pragma unroll
                for (int mi=0;mi<2;mi++){
                    asm volatile(
                      "mma.sync.aligned.m16n8k8.row.col.f32.tf32.tf32.f32 "
                      "{%0,%1,%2,%3},{%4,%5,%6,%7},{%8,%9},{%0,%1,%2,%3};"
                      : "+f"(d[mi][nj][0]),"+f"(d[mi][nj][1]),"+f"(d[mi][nj][2]),"+f"(d[mi][nj][3])
                      : "r"(a[mi][0]),"r"(a[mi][1]),"r"(a[mi][2]),"r"(a[mi][3]),"r"(b0),"r"(b1));
                }
            }
        }
        __syncthreads();
    }
#undef KSTAGE

    float* ep = &As[0][0][0] + w*640;
#pragma unroll
    for (int h=0; h<4; h++){
#pragma unroll
        for (int mi=0;mi<2;mi++){
#pragma unroll
            for (int njl=0;njl<2;njl++){
                int nj = h*2 + njl;
                int r0 = mi*16 + lr;
                ep[ r0   *20 + njl*8 + lc*2    ] = d[mi][nj][0];
                ep[ r0   *20 + njl*8 + lc*2 + 1] = d[mi][nj][1];
                ep[(r0+8)*20 + njl*8 + lc*2    ] = d[mi][nj][2];
                ep[(r0+8)*20 + njl*8 + lc*2 + 1] = d[mi][nj][3];
            }
        }
        __syncwarp();
#pragma unroll
        for (int q=0;q<4;q++){
            int idx = q*32 + lane;
            int r = idx>>2, c4 = idx&3;
            float4 vv = *reinterpret_cast<float4*>(&ep[r*20 + c4*4]);
            size_t nn = (size_t)n0 + wn + h*16 + c4*4;
            float4 bb = *reinterpret_cast<const float4*>(&bias[nn]);
            vv.x+=bb.x; vv.y+=bb.y; vv.z+=bb.z; vv.w+=bb.w;
            __half2 p0 = __floats2half2_rn(vv.x, vv.y);
            __half2 p1 = __floats2half2_rn(vv.z, vv.w);
            uint2 st;
            st.x = reinterpret_cast<unsigned&>(p0);
            st.y = reinterpret_cast<unsigned&>(p1);
            *reinterpret_cast<uint2*>(&g_kph[(size_t)(m0+wm+r)*HH + nn]) = st;
        }
        __syncwarp();
    }
}

// scores: one warp per (b, s); grid (32, 32); keyproj read as fp16; PDL
__global__ __launch_bounds__(256) void scores_kernel(const float* __restrict__ v)
{
    const int b = blockIdx.x, tid = threadIdx.x;
    const int w = tid>>5, lane = tid&31;
    __shared__ __align__(16) float qs[512], vsm[512];
    vsm[tid]     = v[tid];          // static input — safe pre-wait
    vsm[tid+256] = v[tid+256];
    gdep_wait();
    qs[tid]      = g_qp[b*HH+tid];
    qs[tid+256]  = g_qp[b*HH+tid+256];
    __syncthreads();
    const int s = blockIdx.y*8 + w;
    const __half* kp = g_kph + ((size_t)(b*SS+s))*HH;
    float acc = 0.f;
#pragma unroll
    for (int i=0;i<4;i++){
        int h = i*128 + lane*4;
        uint2 kk = *reinterpret_cast<const uint2*>(kp + h);
        float2 f01 = __half22float2(*reinterpret_cast<const __half2*>(&kk.x));
        float2 f23 = __half22float2(*reinterpret_cast<const __half2*>(&kk.y));
        float4 q4 = *reinterpret_cast<const float4*>(&qs[h]);
        float4 v4 = *reinterpret_cast<const float4*>(&vsm[h]);
        acc = fmaf(v4.x, tanh_fast(f01.x+q4.x), acc);
        acc = fmaf(v4.y, tanh_fast(f01.y+q4.y), acc);
        acc = fmaf(v4.z, tanh_fast(f23.x+q4.z), acc);
        acc = fmaf(v4.w, tanh_fast(f23.y+q4.w), acc);
    }
#pragma unroll
    for (int o=16;o;o>>=1) acc += __shfl_xor_sync(0xffffffffu, acc, o);
    if (lane == 0) g_scores[b*SS+s] = acc;
}

// softmax + 64-col context chunk (enc fp16) + emb gather; grid (32, 8); PDL
__global__ __launch_bounds__(256) void smctx_kernel(
    const int* __restrict__ tok, const float* __restrict__ emb, int t)
{
    const int b = blockIdx.x, chunk = blockIdx.y, tid = threadIdx.x;
    const int w = tid>>5, lane = tid&31;
    __shared__ __align__(16) float wsm[SS];
    __shared__ __align__(16) float cpart[4][64];
    __shared__ float red[8];
    __shared__ float smax_s, sinv_s;
    gdep_wait();
    float x = g_scores[b*SS+tid];
    float m = x;
#pragma unroll
    for (int o=16;o;o>>=1) m = fmaxf(m, __shfl_xor_sync(0xffffffffu, m, o));
    if (lane==0) red[w]=m;
    __syncthreads();
    if (tid==0){ float mm=red[0];
#pragma unroll
        for (int i=1;i<8;i++) mm=fmaxf(mm,red[i]); smax_s=mm; }
    __syncthreads();
    float ex = __expf(x - smax_s);
    float s2 = ex;
#pragma unroll
    for (int o=16;o;o>>=1) s2 += __shfl_xor_sync(0xffffffffu, s2, o);
    if (lane==0) red[w]=s2;
    __syncthreads();
    if (tid==0){ float ss=0.f;
#pragma unroll
        for (int i=0;i<8;i++) ss+=red[i]; sinv_s=1.f/ss; }
    __syncthreads();
    wsm[tid] = ex*sinv_s;
    if (chunk == 0){
        int row = tok[b*TT+t];
        g_xcat0[b*K0+tid] = emb[(size_t)row*EEMB+tid];
    }
    __syncthreads();
    const int el = tid & 63, sq = tid >> 6;
    const int e = chunk*64 + el;
    const __half* eb = g_ench + ((size_t)(b*SS) + sq*64)*EENC + e;
    float acc = 0.f;
#pragma unroll 4
    for (int s=0;s<64;s++) acc = fmaf(wsm[sq*64+s], __half2float(eb[(size_t)s*EENC]), acc);
    cpart[sq][el] = acc;
    __syncthreads();
    if (tid < 64){
        float ctx = cpart[0][tid]+cpart[1][tid]+cpart[2][tid]+cpart[3][tid];
        g_xcat0[b*K0 + 256 + e] = ctx;
        g_Xall[((size_t)(b*TT+t))*KL + 512 + e] = tf32r(ctx);
    }
}

// gates split-K via tf32 MMA with hi/lo compensation; PDL
__global__ __launch_bounds__(256) void gates_mma(
    const float* __restrict__ X, const float* __restrict__ Whi,
    const float* __restrict__ Wlo, float* __restrict__ Cp, int K)
{
    __shared__ __align__(16) float Xh[32][36], Xl[32][36];
    __shared__ __align__(16) float Bh[128][36], Bl[128][36];
    const int tid = threadIdx.x, lane = tid&31, w = tid>>5;
    const int lr = lane>>2, lc = lane&3;
    const int j0 = blockIdx.x*128;
    const int k0 = blockIdx.y*128;
    float d[2][2][4] = {};
    gdep_wait();

    for (int kt = 0; kt < 4; ++kt){
        const int kk = k0 + kt*32;
        {
            int r = tid>>3, c = (tid&7)*4;
            float4 xv = *reinterpret_cast<const float4*>(X + (size_t)r*K + kk + c);
            float4 hi, lo;
            hi.x=tf32r(xv.x); lo.x=tf32r(xv.x-hi.x);
            hi.y=tf32r(xv.y); lo.y=tf32r(xv.y-hi.y);
            hi.z=tf32r(xv.z); lo.z=tf32r(xv.z-hi.z);
            hi.w=tf32r(xv.w); lo.w=tf32r(xv.w-hi.w);
            *reinterpret_cast<float4*>(&Xh[r][c]) = hi;
            *reinterpret_cast<float4*>(&Xl[r][c]) = lo;
        }
#pragma unroll
        for (int i=0;i<4;i++){
            int f = tid + i*256;
            int r = f>>3, c = (f&7)*4;
            *reinterpret_cast<float4*>(&Bh[r][c]) =
                *reinterpret_cast<const float4*>(Whi + (size_t)(j0+r)*K + kk + c);
            *reinterpret_cast<float4*>(&Bl[r][c]) =
                *reinterpret_cast<const float4*>(Wlo + (size_t)(j0+r)*K + kk + c);
        }
        __syncthreads();
#pragma unroll
        for (int k8=0;k8<4;k8++){
            const int co = k8*8;
            unsigned ah[2][4], al[2][4];
#pragma unroll
            for (int mi=0;mi<2;mi++){
                int rb = mi*16 + lr;
                ah[mi][0]=__float_as_uint(Xh[rb  ][co+lc]);
                ah[mi][1]=__float_as_uint(Xh[rb+8][co+lc]);
                ah[mi][2]=__float_as_uint(Xh[rb  ][co+lc+4]);
                ah[mi][3]=__float_as_uint(Xh[rb+8][co+lc+4]);
                al[mi][0]=__float_as_uint(Xl[rb  ][co+lc]);
                al[mi][1]=__float_as_uint(Xl[rb+8][co+lc]);
                al[mi][2]=__float_as_uint(Xl[rb  ][co+lc+4]);
                al[mi][3]=__float_as_uint(Xl[rb+8][co+lc+4]);
            }
#pragma unroll
            for (int nj=0;nj<2;nj++){
                int nb = w*16 + nj*8 + lr;
                unsigned bh0 = __float_as_uint(Bh[nb][co+lc]);
                unsigned bh1 = __float_as_uint(Bh[nb][co+lc+4]);
                unsigned bl0 = __float_as_uint(Bl[nb][co+lc]);
                unsigned bl1 = __float_as_uint(Bl[nb][co+lc+4]);
#pragma unroll
                for (int mi=0;mi<2;mi++){
#define GMMA(AA,B0,B1) asm volatile( \
    "mma.sync.aligned.m16n8k8.row.col.f32.tf32.tf32.f32 " \
    "{%0,%1,%2,%3},{%4,%5,%6,%7},{%8,%9},{%0,%1,%2,%3};" \
    : "+f"(d[mi][nj][0]),"+f"(d[mi][nj][1]),"+f"(d[mi][nj][2]),"+f"(d[mi][nj][3]) \
    : "r"(AA[mi][0]),"r"(AA[mi][1]),"r"(AA[mi][2]),"r"(AA[mi][3]),"r"(B0),"r"(B1))
                    GMMA(ah, bh0, bh1);
                    GMMA(ah, bl0, bl1);
                    GMMA(al, bh0, bh1);
#undef GMMA
                }
            }
        }
        __syncthreads();
    }
    float* out = Cp + blockIdx.y*65536;
#pragma unroll
    for (int mi=0;mi<2;mi++){
#pragma unroll
        for (int nj=0;nj<2;nj++){
            int col = j0 + w*16 + nj*8 + lc*2;
            int m  = mi*16 + lr;
            *reinterpret_cast<float2*>(&out[(size_t)m*2048 + col])     = make_float2(d[mi][nj][0], d[mi][nj][1]);
            *reinterpret_cast<float2*>(&out[(size_t)(m+8)*2048 + col]) = make_float2(d[mi][nj][2], d[mi][nj][3]);
        }
    }
}

__global__ __launch_bounds__(512) void cell0_kernel()
{
    const int b = blockIdx.x, u = threadIdx.x;
    gdep_wait();
    float gi=g_bcat0[u], gf=g_bcat0[512+u], gg=g_bcat0[1024+u], go=g_bcat0[1536+u];
#pragma unroll
    for (int s=0;s<10;s++){
        const float* p = g_part0 + s*65536 + b*2048;
        gi += p[u]; gf += p[512+u]; gg += p[1024+u]; go += p[1536+u];
    }
    float c = sigf(gf)*g_c0[b*HH+u] + sigf(gi)*tanh_acc(gg);
    float h = sigf(go)*tanh_acc(c);
    g_c0[b*HH+u] = c;
    g_xcat0[b*K0 + 768 + u] = h;
    g_xcat1[b*K1 + u]       = h;
}

__global__ __launch_bounds__(512) void cell1_kernel(const float* __restrict__ bq, int t)
{
    const int b = blockIdx.x, u = threadIdx.x;
    __shared__ __align__(16) float h1s[512];
    __shared__ __align__(16) float qpart[4][512];
    gdep_wait();
    float gi=g_bcat1[u], gf=g_bcat1[512+u], gg=g_bcat1[1024+u], go=g_bcat1[1536+u];
#pragma unroll
    for (int s=0;s<8;s++){
        const float* p = g_part1 + s*65536 + b*2048;
        gi += p[u]; gf += p[512+u]; gg += p[1024+u]; go += p[1536+u];
    }
    float c = sigf(gf)*g_c1[b*HH+u] + sigf(gi)*tanh_acc(gg);
    float h = sigf(go)*tanh_acc(c);
    g_c1[b*HH+u] = c;
    g_h1[b*HH+u] = h;
    g_xcat1[b*K1 + 512 + u] = h;
    g_Xall[((size_t)(b*TT+t))*KL + u] = tf32r(h);
    h1s[u] = h;
    __syncthreads();
    const int h4 = (u & 127)*4, kp = u >> 7;
    float4 a = make_float4(0.f,0.f,0.f,0.f);
    const float* wb = g_Wqt + (size_t)kp*128*HH + h4;
#pragma unroll 4
    for (int k=0;k<128;k++){
        float4 w4 = *reinterpret_cast<const float4*>(wb + (size_t)k*HH);
        float xv = h1s[kp*128 + k];
        a.x=fmaf(w4.x,xv,a.x); a.y=fmaf(w4.y,xv,a.y);
        a.z=fmaf(w4.z,xv,a.z); a.w=fmaf(w4.w,xv,a.w);
    }
    *reinterpret_cast<float4*>(&qpart[kp][h4]) = a;
    __syncthreads();
    g_qp[b*HH+u] = qpart[0][u]+qpart[1][u]+qpart[2][u]+qpart[3][u] + bq[u];
}

// logits v3: tf32 mma, BM128 x BN128 x BK16, 3-stage cp.async (dynamic smem)
__global__ __launch_bounds__(256) void logits_mma(
    const float* __restrict__ A, const float* __restrict__ B,
    const float* __restrict__ bias, float* __restrict__ C)
{
    extern __shared__ __align__(16) float smem_l[];
    float (*As)[128][20] = reinterpret_cast<float(*)[128][20]>(smem_l);
    float (*Bs)[128][20] = reinterpret_cast<float(*)[128][20]>(smem_l + 3*128*20);
    const int tid = threadIdx.x, lane = tid&31, w = tid>>5;
    const int wm = (w&3)*32, wn = (w>>2)*64;
    const int m0 = blockIdx.x*128, n0 = blockIdx.y*128;
    const int lr = lane>>2, lc = lane&3;
    float d[2][8][4] = {};

#define STAGE(bufi, kt) do { \
    int kk = (kt)*16; \
    _Pragma("unroll") \
    for (int i=0;i<2;i++){ \
        int f = tid + i*256; int r = f>>2, c = f&3; \
        unsigned dst = (unsigned)__cvta_generic_to_shared(&As[bufi][r][c*4]); \
        const float* src = A + (size_t)(m0+r)*KL + kk + c*4; \
        asm volatile("cp.async.cg.shared.global [%0], [%1], 16;"::"r"(dst),"l"(src)); \
    } \
    _Pragma("unroll") \
    for (int i=0;i<2;i++){ \
        int f = tid + i*256; int r = f>>2, c = f&3; \
        unsigned dst = (unsigned)__cvta_generic_to_shared(&Bs[bufi][r][c*4]); \
        const float* src = B + (size_t)(n0+r)*KL + kk + c*4; \
        asm volatile("cp.async.cg.shared.global [%0], [%1], 16;"::"r"(dst),"l"(src)); \
    } \
    asm volatile("cp.async.commit_group;"); \
} while(0)

    STAGE(0, 0);
    STAGE(1, 1);
    const int KT = KL/16;
    for (int kt=0; kt<KT; ++kt){
        const int buf = kt % 3;
        if (kt == KT-1) asm volatile("cp.async.wait_group 0;");
        else            asm volatile("cp.async.wait_group 1;");
        __syncthreads();
        if (kt+2 < KT) STAGE((kt+2)%3, kt+2);
#pragma unroll
        for (int k8=0;k8<2;k8++){
            const int co = k8*8;
            unsigned a[2][4];
#pragma unroll
            for (int mi=0;mi<2;mi++){
                int rb = wm + mi*16 + lr;
                a[mi][0] = __float_as_uint(As[buf][rb  ][co+lc]);
                a[mi][1] = __float_as_uint(As[buf][rb+8][co+lc]);
                a[mi][2] = __float_as_uint(As[buf][rb  ][co+lc+4]);
                a[mi][3] = __float_as_uint(As[buf][rb+8][co+lc+4]);
            }
#pragma unroll
            for (int nj=0;nj<8;nj++){
                int nb = wn + nj*8 + lr;
                unsigned b0 = __float_as_uint(Bs[buf][nb][co+lc]);
                unsigned b1 = __float_as_uint(Bs[buf][nb][co+lc+4]);
#pragma unroll
                for (int mi=0;mi<2;mi++){
                    asm volatile(
                      "mma.sync.aligned.m16n8k8.row.col.f32.tf32.tf32.f32 "
                      "{%0,%1,%2,%3},{%4,%5,%6,%7},{%8,%9},{%0,%1,%2,%3};"
                      : "+f"(d[mi][nj][0]),"+f"(d[mi][nj][1]),"+f"(d[mi][nj][2]),"+f"(d[mi][nj][3])
                      : "r"(a[mi][0]),"r"(a[mi][1]),"r"(a[mi][2]),"r"(a[mi][3]),"r"(b0),"r"(b1));
                }
            }
        }
    }
#undef STAGE
    __syncthreads();

    float* ep = smem_l + w*640;
#pragma unroll
    for (int h=0; h<4; h++){
#pragma unroll
        for (int mi=0;mi<2;mi++){
#pragma unroll
            for (int njl=0;njl<2;njl++){
                int nj = h*2 + njl;
                int r0 = mi*16 + lr;
                ep[ r0   *20 + njl*8 + lc*2    ] = d[mi][nj][0];
                ep[ r0   *20 + njl*8 + lc*2 + 1] = d[mi][nj][1];
                ep[(r0+8)*20 + njl*8 + lc*2    ] = d[mi][nj][2];
                ep[(r0+8)*20 + njl*8 + lc*2 + 1] = d[mi][nj][3];
            }
        }
        __syncwarp();
#pragma unroll
        for (int q=0;q<4;q++){
            int idx = q*32 + lane;
            int r = idx>>2, c4 = idx&3;
            float4 vv = *reinterpret_cast<float4*>(&ep[r*20 + c4*4]);
            size_t nn = (size_t)n0 + wn + h*16 + c4*4;
            float4 bb = *reinterpret_cast<const float4*>(&bias[nn]);
            vv.x+=bb.x; vv.y+=bb.y; vv.z+=bb.z; vv.w+=bb.w;
            *reinterpret_cast<float4*>(&C[(size_t)(m0+wm+r)*VV + nn]) = vv;
        }
        __syncwarp();
    }
}

__global__ __launch_bounds__(512) void tail_kernel(float* __restrict__ out)
{
    int idx = blockIdx.x*blockDim.x + threadIdx.x;
    int part = idx / (BB*HH);
    int off  = idx % (BB*HH);
    int b = off / HH, u = off % HH;
    float val;
    if      (part == 0) val = g_xcat1[b*K1 + u];
    else if (part == 1) val = g_h1[off];
    else if (part == 2) val = g_c0[off];
    else                val = g_c1[off];
    out[OUT_TAIL_OFF + idx] = val;
}

// PDL launch helper
template <typename K, typename... Args>
static inline void launch_pdl(K kern, dim3 grid, dim3 block, Args... args)
{
    cudaLaunchConfig_t cfg = {};
    cfg.gridDim = grid;
    cfg.blockDim = block;
    cfg.dynamicSmemBytes = 0;
    cfg.stream = 0;
    cudaLaunchAttribute at[1];
    at[0].id = cudaLaunchAttributeProgrammaticStreamSerialization;
    at[0].val.programmaticStreamSerializationAllowed = 1;
    cfg.attrs = at;
    cfg.numAttrs = 1;
    cudaLaunchKernelEx(&cfg, kern, args...);
}

extern "C" void kernel_launch(void* const* d_in, const int* in_sizes, int n_in,
                              void* d_out, int out_size)
{
    const float* enc  = (const float*)d_in[0];
    const int*   tok  = (const int*)  d_in[1];
    const float* emb  = (const float*)d_in[2];
    const float* Wq   = (const float*)d_in[3];
    const float* bq   = (const float*)d_in[4];
    const float* Wk   = (const float*)d_in[5];
    const float* bk   = (const float*)d_in[6];
    const float* v    = (const float*)d_in[7];
    const float* Wih0 = (const float*)d_in[8];
    const float* Whh0 = (const float*)d_in[9];
    const float* bih0 = (const float*)d_in[10];
    const float* bhh0 = (const float*)d_in[11];
    const float* Wih1 = (const float*)d_in[12];
    const float* Whh1 = (const float*)d_in[13];
    const float* bih1 = (const float*)d_in[14];
    const float* bhh1 = (const float*)d_in[15];
    const float* Wout = (const float*)d_in[16];
    const float* bout = (const float*)d_in[17];
    float* out = (float*)d_out;

    float *p_W0hi, *p_W0lo, *p_W1hi, *p_W1lo, *p_Wt32;
    float *p_xcat0, *p_xcat1, *p_part0, *p_part1, *p_Xall;
    cudaGetSymbolAddress((void**)&p_W0hi,  g_W0hi);
    cudaGetSymbolAddress((void**)&p_W0lo,  g_W0lo);
    cudaGetSymbolAddress((void**)&p_W1hi,  g_W1hi);
    cudaGetSymbolAddress((void**)&p_W1lo,  g_W1lo);
    cudaGetSymbolAddress((void**)&p_Wt32,  g_Wt32);
    cudaGetSymbolAddress((void**)&p_xcat0, g_xcat0);
    cudaGetSymbolAddress((void**)&p_xcat1, g_xcat1);
    cudaGetSymbolAddress((void**)&p_part0, g_part0);
    cudaGetSymbolAddress((void**)&p_part1, g_part1);
    cudaGetSymbolAddress((void**)&p_Xall,  g_Xall);

    cudaFuncSetAttribute(logits_mma, cudaFuncAttributeMaxDynamicSharedMemorySize, 3*2*128*20*4);

    init_kernel<<<2048, 256>>>(Wih0, Whh0, bih0, bhh0, Wih1, Whh1, bih1, bhh1, Wq, bq);
    cvt_wout<<<2048, 256>>>(Wout);
    cvt_enc<<<2048, 256>>>(enc);
    keyproj_mma<<<dim3(64, 4), 256>>>(enc, Wk, bk);

    for (int t = 0; t < TT; ++t){
        launch_pdl(scores_kernel, dim3(BB, 32), dim3(256), v);
        launch_pdl(smctx_kernel,  dim3(BB, 8),  dim3(256), tok, emb, t);
        launch_pdl(gates_mma, dim3(16, 10), dim3(256),
                   (const float*)p_xcat0, (const float*)p_W0hi, (const float*)p_W0lo, p_part0, (int)K0);
        launch_pdl(cell0_kernel, dim3(BB), dim3(512));
        launch_pdl(gates_mma, dim3(16, 8), dim3(256),
                   (const float*)p_xcat1, (const float*)p_W1hi, (const float*)p_W1lo, p_part1, (int)K1);
        launch_pdl(cell1_kernel, dim3(BB), dim3(512), bq, t);
    }

    {   // logits = Xall(4096x1024) @ Wt32^T + bout  (m-major grid for B-tile reuse)
        dim3 grid((BB*TT)/128, VV/128);
        logits_mma<<<grid, 256, 3*2*128*20*4>>>(p_Xall, p_Wt32, bout, out);
    }
    tail_kernel<<<128, 512>>>(out);
}

// round 17
// speedup vs baseline: 1.5803x; 1.0350x over previous
#include <cuda_runtime.h>
#include <cuda_fp16.h>
#include <cstdint>

#define BB 32
#define SS 256
#define TT 128
#define EENC 512
#define HH 512
#define EEMB 256
#define VV 32000
#define KC 1024          // gates K for both layers: [ctx|h0] and [h0|h1]
#define KL 1024
#define OUT_TAIL_OFF 131072000ll

__device__ __half g_kph[BB*SS*HH];
__device__ __half g_ench[BB*SS*EENC];
__device__ float g_W0hi[2048*KC];     // [ctx(512) | h0(512)]
__device__ float g_W0lo[2048*KC];
__device__ float g_W1hi[2048*KC];     // [h0(512) | h1(512)]
__device__ float g_W1lo[2048*KC];
__device__ float g_WEhi[2048*EEMB];   // emb part of Wih0
__device__ float g_WElo[2048*EEMB];
__device__ float g_bcat0[2048];
__device__ float g_bcat1[2048];
__device__ float g_Wqt[HH*HH];
__device__ float g_embg0[(size_t)BB*TT*2048];  // precomputed emb-gate + bias
__device__ float g_xcat0[BB*KC];   // [ctx | h0(prev)]
__device__ float g_xcat1[BB*KC];   // [h0 | h1(prev)]
__device__ float g_part0[8*BB*2048];
__device__ float g_part1[8*BB*2048];
__device__ float g_h1[BB*HH];
__device__ float g_c0[BB*HH];
__device__ float g_c1[BB*HH];
__device__ float g_qp[BB*HH];
__device__ float g_scores[BB*SS];
__device__ float g_Xall[(size_t)BB*TT*KL];

__device__ __forceinline__ float tanh_acc(float x){
    float xx = fminf(15.f, fmaxf(-15.f, x));
    float e  = __expf(2.f*xx);
    return 1.f - __fdividef(2.f, e + 1.f);
}
__device__ __forceinline__ float sigf(float x){
    float xx = fminf(30.f, fmaxf(-30.f, x));
    return __fdividef(1.f, 1.f + __expf(-xx));
}
__device__ __forceinline__ float tanh_fast(float x){
    float y; asm("tanh.approx.f32 %0, %1;" : "=f"(y) : "f"(x));
    return y;
}
__device__ __forceinline__ float tf32r(float x){
    unsigned u; asm("cvt.rna.tf32.f32 %0, %1;" : "=r"(u) : "f"(x));
    return __uint_as_float(u);
}
__device__ __forceinline__ void gdep_wait(){
    asm volatile("griddepcontrol.wait;" ::: "memory");
}

__global__ void init_kernel(const float* __restrict__ Wih0, const float* __restrict__ Whh0,
                            const float* __restrict__ bih0, const float* __restrict__ bhh0,
                            const float* __restrict__ Wih1, const float* __restrict__ Whh1,
                            const float* __restrict__ bih1, const float* __restrict__ bhh1,
                            const float* __restrict__ Wq,   const float* __restrict__ bq)
{
    const int NW0=2048*KC, NW1=2048*KC, NWE=2048*EEMB, NB=2048, NWQ=HH*HH, NQP=BB*HH;
    const int NZ = BB*HH*3 + BB*KC*2;
    const int TOT = NW0+NW1+NWE+2*NB+NWQ+NQP+NZ;
    for (int idx = blockIdx.x*blockDim.x+threadIdx.x; idx < TOT; idx += gridDim.x*blockDim.x){
        int r = idx;
        if (r < NW0){
            int j=r/KC,k=r%KC;
            float w = (k<512) ? Wih0[j*768 + 256 + k] : Whh0[j*512 + (k-512)];
            float hi = tf32r(w);
            g_W0hi[r] = hi; g_W0lo[r] = tf32r(w - hi);
            continue;
        }
        r -= NW0;
        if (r < NW1){
            int j=r/KC,k=r%KC;
            float w = (k<512) ? Wih1[j*512+k] : Whh1[j*512+(k-512)];
            float hi = tf32r(w);
            g_W1hi[r] = hi; g_W1lo[r] = tf32r(w - hi);
            continue;
        }
        r -= NW1;
        if (r < NWE){
            int j=r/EEMB,k=r%EEMB;
            float w = Wih0[j*768 + k];
            float hi = tf32r(w);
            g_WEhi[r] = hi; g_WElo[r] = tf32r(w - hi);
            continue;
        }
        r -= NWE;
        if (r < NB){ g_bcat0[r]=bih0[r]+bhh0[r]; continue; }
        r -= NB;
        if (r < NB){ g_bcat1[r]=bih1[r]+bhh1[r]; continue; }
        r -= NB;
        if (r < NWQ){ int k=r/HH,h=r%HH; g_Wqt[r]=Wq[h*HH+k]; continue; }
        r -= NWQ;
        if (r < NQP){ g_qp[r]=bq[r%HH]; continue; }
        r -= NQP;
        if (r < BB*HH){ g_h1[r]=0.f; continue; }
        r -= BB*HH;
        if (r < BB*HH){ g_c0[r]=0.f; continue; }
        r -= BB*HH;
        if (r < BB*HH){ g_c1[r]=0.f; continue; }
        r -= BB*HH;
        if (r < BB*KC){ g_xcat0[r]=0.f; continue; }
        r -= BB*KC;
        g_xcat1[r]=0.f;
    }
}

__global__ void cvt_enc(const float* __restrict__ enc)
{
    int n = BB*SS*EENC/2;
    for (int i = blockIdx.x*blockDim.x+threadIdx.x; i < n; i += gridDim.x*blockDim.x){
        float2 f = reinterpret_cast<const float2*>(enc)[i];
        reinterpret_cast<__half2*>(g_ench)[i] = __floats2half2_rn(f.x, f.y);
    }
}

// keyproj via tf32 MMA: g_kph = fp16( enc(8192x512) @ Wk^T + bk ); grid (64, 4)
__global__ __launch_bounds__(256) void keyproj_mma(
    const float* __restrict__ A, const float* __restrict__ B,
    const float* __restrict__ bias)
{
    __shared__ __align__(16) float As[2][128][20];
    __shared__ __align__(16) float Bs[2][128][20];
    const int tid = threadIdx.x, lane = tid&31, w = tid>>5;
    const int wm = (w&3)*32, wn = (w>>2)*64;
    const int m0 = blockIdx.x*128, n0 = blockIdx.y*128;
    const int lr = lane>>2, lc = lane&3;
    float d[2][8][4] = {};

#define KSTAGE(bufi, kt) do { \
    int kk = (kt)*16; \
    _Pragma("unroll") \
    for (int i=0;i<2;i++){ \
        int f = tid + i*256; int r = f>>2, c = f&3; \
        unsigned dst = (unsigned)__cvta_generic_to_shared(&As[bufi][r][c*4]); \
        const float* src = A + (size_t)(m0+r)*EENC + kk + c*4; \
        asm volatile("cp.async.cg.shared.global [%0], [%1], 16;"::"r"(dst),"l"(src)); \
    } \
    _Pragma("unroll") \
    for (int i=0;i<2;i++){ \
        int f = tid + i*256; int r = f>>2, c = f&3; \
        unsigned dst = (unsigned)__cvta_generic_to_shared(&Bs[bufi][r][c*4]); \
        const float* src = B + (size_t)(n0+r)*EENC + kk + c*4; \
        asm volatile("cp.async.cg.shared.global [%0], [%1], 16;"::"r"(dst),"l"(src)); \
    } \
    asm volatile("cp.async.commit_group;"); \
} while(0)

    KSTAGE(0, 0);
    const int KT = EENC/16;
    for (int kt=0; kt<KT; ++kt){
        const int buf = kt&1;
        if (kt+1 < KT){ KSTAGE(buf^1, kt+1); asm volatile("cp.async.wait_group 1;"); }
        else          { asm volatile("cp.async.wait_group 0;"); }
        __syncthreads();
#pragma unroll
        for (int k8=0;k8<2;k8++){
            const int co = k8*8;
            unsigned a[2][4];
#pragma unroll
            for (int mi=0;mi<2;mi++){
                int rb = wm + mi*16 + lr;
                a[mi][0] = __float_as_uint(tf32r(As[buf][rb  ][co+lc]));
                a[mi][1] = __float_as_uint(tf32r(As[buf][rb+8][co+lc]));
                a[mi][2] = __float_as_uint(tf32r(As[buf][rb  ][co+lc+4]));
                a[mi][3] = __float_as_uint(tf32r(As[buf][rb+8][co+lc+4]));
            }
#pragma unroll
            for (int nj=0;nj<8;nj++){
                int nb = wn + nj*8 + lr;
                unsigned b0 = __float_as_uint(tf32r(Bs[buf][nb][co+lc]));
                unsigned b1 = __float_as_uint(tf32r(Bs[buf][nb][co+lc+4]));
#pragma unroll
                for (int mi=0;mi<2;mi++){
                    asm volatile(
                      "mma.sync.aligned.m16n8k8.row.col.f32.tf32.tf32.f32 "
                      "{%0,%1,%2,%3},{%4,%5,%6,%7},{%8,%9},{%0,%1,%2,%3};"
                      : "+f"(d[mi][nj][0]),"+f"(d[mi][nj][1]),"+f"(d[mi][nj][2]),"+f"(d[mi][nj][3])
                      : "r"(a[mi][0]),"r"(a[mi][1]),"r"(a[mi][2]),"r"(a[mi][3]),"r"(b0),"r"(b1));
                }
            }
        }
        __syncthreads();
    }
#undef KSTAGE

    float* ep = &As[0][0][0] + w*640;
#pragma unroll
    for (int h=0; h<4; h++){
#pragma unroll
        for (int mi=0;mi<2;mi++){
#pragma unroll
            for (int njl=0;njl<2;njl++){
                int nj = h*2 + njl;
                int r0 = mi*16 + lr;
                ep[ r0   *20 + njl*8 + lc*2    ] = d[mi][nj][0];
                ep[ r0   *20 + njl*8 + lc*2 + 1] = d[mi][nj][1];
                ep[(r0+8)*20 + njl*8 + lc*2    ] = d[mi][nj][2];
                ep[(r0+8)*20 + njl*8 + lc*2 + 1] = d[mi][nj][3];
            }
        }
        __syncwarp();
#pragma unroll
        for (int q=0;q<4;q++){
            int idx = q*32 + lane;
            int r = idx>>2, c4 = idx&3;
            float4 vv = *reinterpret_cast<float4*>(&ep[r*20 + c4*4]);
            size_t nn = (size_t)n0 + wn + h*16 + c4*4;
            float4 bb = *reinterpret_cast<const float4*>(&bias[nn]);
            vv.x+=bb.x; vv.y+=bb.y; vv.z+=bb.z; vv.w+=bb.w;
            __half2 p0 = __floats2half2_rn(vv.x, vv.y);
            __half2 p1 = __floats2half2_rn(vv.z, vv.w);
            uint2 st;
            st.x = reinterpret_cast<unsigned&>(p0);
            st.y = reinterpret_cast<unsigned&>(p1);
            *reinterpret_cast<uint2*>(&g_kph[(size_t)(m0+wm+r)*HH + nn]) = st;
        }
        __syncwarp();
    }
}

// embg: g_embg0[m][j] = emb[tok[m]] @ WE^T + bcat0, m=b*TT+t; grid (16 j-tiles, 128 m-tiles)
// hi/lo tf32 compensation; clone of gates_mma structure with gathered A and K=256.
__global__ __launch_bounds__(256) void embg_mma(
    const float* __restrict__ emb, const int* __restrict__ tok)
{
    __shared__ __align__(16) float Xh[32][36], Xl[32][36];
    __shared__ __align__(16) float Bh[128][36], Bl[128][36];
    const int tid = threadIdx.x, lane = tid&31, w = tid>>5;
    const int lr = lane>>2, lc = lane&3;
    const int j0 = blockIdx.x*128;
    const int m0 = blockIdx.y*32;
    float d[2][2][4] = {};

    for (int kt = 0; kt < 8; ++kt){
        const int kk = kt*32;
        {
            int r = tid>>3, c = (tid&7)*4;
            float4 xv = *reinterpret_cast<const float4*>(emb + (size_t)tok[m0+r]*EEMB + kk + c);
            float4 hi, lo;
            hi.x=tf32r(xv.x); lo.x=tf32r(xv.x-hi.x);
            hi.y=tf32r(xv.y); lo.y=tf32r(xv.y-hi.y);
            hi.z=tf32r(xv.z); lo.z=tf32r(xv.z-hi.z);
            hi.w=tf32r(xv.w); lo.w=tf32r(xv.w-hi.w);
            *reinterpret_cast<float4*>(&Xh[r][c]) = hi;
            *reinterpret_cast<float4*>(&Xl[r][c]) = lo;
        }
#pragma unroll
        for (int i=0;i<4;i++){
            int f = tid + i*256;
            int r = f>>3, c = (f&7)*4;
            *reinterpret_cast<float4*>(&Bh[r][c]) =
                *reinterpret_cast<const float4*>(g_WEhi + (size_t)(j0+r)*EEMB + kk + c);
            *reinterpret_cast<float4*>(&Bl[r][c]) =
                *reinterpret_cast<const float4*>(g_WElo + (size_t)(j0+r)*EEMB + kk + c);
        }
        __syncthreads();
#pragma unroll
        for (int k8=0;k8<4;k8++){
            const int co = k8*8;
            unsigned ah[2][4], al[2][4];
#pragma unroll
            for (int mi=0;mi<2;mi++){
                int rb = mi*16 + lr;
                ah[mi][0]=__float_as_uint(Xh[rb  ][co+lc]);
                ah[mi][1]=__float_as_uint(Xh[rb+8][co+lc]);
                ah[mi][2]=__float_as_uint(Xh[rb  ][co+lc+4]);
                ah[mi][3]=__float_as_uint(Xh[rb+8][co+lc+4]);
                al[mi][0]=__float_as_uint(Xl[rb  ][co+lc]);
                al[mi][1]=__float_as_uint(Xl[rb+8][co+lc]);
                al[mi][2]=__float_as_uint(Xl[rb  ][co+lc+4]);
                al[mi][3]=__float_as_uint(Xl[rb+8][co+lc+4]);
            }
#pragma unroll
            for (int nj=0;nj<2;nj++){
                int nb = w*16 + nj*8 + lr;
                unsigned bh0 = __float_as_uint(Bh[nb][co+lc]);
                unsigned bh1 = __float_as_uint(Bh[nb][co+lc+4]);
                unsigned bl0 = __float_as_uint(Bl[nb][co+lc]);
                unsigned bl1 = __float_as_uint(Bl[nb][co+lc+4]);
#pragma unroll
                for (int mi=0;mi<2;mi++){
#define EMMA(AA,B0,B1) asm volatile( \
    "mma.sync.aligned.m16n8k8.row.col.f32.tf32.tf32.f32 " \
    "{%0,%1,%2,%3},{%4,%5,%6,%7},{%8,%9},{%0,%1,%2,%3};" \
    : "+f"(d[mi][nj][0]),"+f"(d[mi][nj][1]),"+f"(d[mi][nj][2]),"+f"(d[mi][nj][3]) \
    : "r"(AA[mi][0]),"r"(AA[mi][1]),"r"(AA[mi][2]),"r"(AA[mi][3]),"r"(B0),"r"(B1))
                    EMMA(ah, bh0, bh1);
                    EMMA(ah, bl0, bl1);
                    EMMA(al, bh0, bh1);
#undef EMMA
                }
            }
        }
        __syncthreads();
    }
    float* out = g_embg0 + (size_t)m0*2048;
#pragma unroll
    for (int mi=0;mi<2;mi++){
#pragma unroll
        for (int nj=0;nj<2;nj++){
            int col = j0 + w*16 + nj*8 + lc*2;
            int m  = mi*16 + lr;
            float2 b2 = *reinterpret_cast<const float2*>(&g_bcat0[col]);
            *reinterpret_cast<float2*>(&out[(size_t)m*2048 + col]) =
                make_float2(d[mi][nj][0]+b2.x, d[mi][nj][1]+b2.y);
            *reinterpret_cast<float2*>(&out[(size_t)(m+8)*2048 + col]) =
                make_float2(d[mi][nj][2]+b2.x, d[mi][nj][3]+b2.y);
        }
    }
}

// scores: one warp per (b, s); grid (32, 32); keyproj fp16; PDL
__global__ __launch_bounds__(256) void scores_kernel(const float* __restrict__ v)
{
    const int b = blockIdx.x, tid = threadIdx.x;
    const int w = tid>>5, lane = tid&31;
    __shared__ __align__(16) float qs[512], vsm[512];
    vsm[tid]     = v[tid];
    vsm[tid+256] = v[tid+256];
    gdep_wait();
    qs[tid]      = g_qp[b*HH+tid];
    qs[tid+256]  = g_qp[b*HH+tid+256];
    __syncthreads();
    const int s = blockIdx.y*8 + w;
    const __half* kp = g_kph + ((size_t)(b*SS+s))*HH;
    float acc = 0.f;
#pragma unroll
    for (int i=0;i<4;i++){
        int h = i*128 + lane*4;
        uint2 kk = *reinterpret_cast<const uint2*>(kp + h);
        float2 f01 = __half22float2(*reinterpret_cast<const __half2*>(&kk.x));
        float2 f23 = __half22float2(*reinterpret_cast<const __half2*>(&kk.y));
        float4 q4 = *reinterpret_cast<const float4*>(&qs[h]);
        float4 v4 = *reinterpret_cast<const float4*>(&vsm[h]);
        acc = fmaf(v4.x, tanh_fast(f01.x+q4.x), acc);
        acc = fmaf(v4.y, tanh_fast(f01.y+q4.y), acc);
        acc = fmaf(v4.z, tanh_fast(f23.x+q4.z), acc);
        acc = fmaf(v4.w, tanh_fast(f23.y+q4.w), acc);
    }
#pragma unroll
    for (int o=16;o;o>>=1) acc += __shfl_xor_sync(0xffffffffu, acc, o);
    if (lane == 0) g_scores[b*SS+s] = acc;
}

// softmax + 64-col context chunk (enc fp16); grid (32, 8); PDL
__global__ __launch_bounds__(256) void smctx_kernel(int t)
{
    const int b = blockIdx.x, chunk = blockIdx.y, tid = threadIdx.x;
    const int w = tid>>5, lane = tid&31;
    __shared__ __align__(16) float wsm[SS];
    __shared__ __align__(16) float cpart[4][64];
    __shared__ float red[8];
    __shared__ float smax_s, sinv_s;
    gdep_wait();
    float x = g_scores[b*SS+tid];
    float m = x;
#pragma unroll
    for (int o=16;o;o>>=1) m = fmaxf(m, __shfl_xor_sync(0xffffffffu, m, o));
    if (lane==0) red[w]=m;
    __syncthreads();
    if (tid==0){ float mm=red[0];
#pragma unroll
        for (int i=1;i<8;i++) mm=fmaxf(mm,red[i]); smax_s=mm; }
    __syncthreads();
    float ex = __expf(x - smax_s);
    float s2 = ex;
#pragma unroll
    for (int o=16;o;o>>=1) s2 += __shfl_xor_sync(0xffffffffu, s2, o);
    if (lane==0) red[w]=s2;
    __syncthreads();
    if (tid==0){ float ss=0.f;
#pragma unroll
        for (int i=0;i<8;i++) ss+=red[i]; sinv_s=1.f/ss; }
    __syncthreads();
    wsm[tid] = ex*sinv_s;
    __syncthreads();
    const int el = tid & 63, sq = tid >> 6;
    const int e = chunk*64 + el;
    const __half* eb = g_ench + ((size_t)(b*SS) + sq*64)*EENC + e;
    float acc = 0.f;
#pragma unroll 4
    for (int s=0;s<64;s++) acc = fmaf(wsm[sq*64+s], __half2float(eb[(size_t)s*EENC]), acc);
    cpart[sq][el] = acc;
    __syncthreads();
    if (tid < 64){
        float ctx = cpart[0][tid]+cpart[1][tid]+cpart[2][tid]+cpart[3][tid];
        g_xcat0[b*KC + e] = ctx;                       // ctx at offset 0
        g_Xall[((size_t)(b*TT+t))*KL + 512 + e] = tf32r(ctx);
    }
}

// gates split-K via tf32 MMA with hi/lo compensation; K=1024; PDL
__global__ __launch_bounds__(256) void gates_mma(
    const float* __restrict__ X, const float* __restrict__ Whi,
    const float* __restrict__ Wlo, float* __restrict__ Cp)
{
    __shared__ __align__(16) float Xh[32][36], Xl[32][36];
    __shared__ __align__(16) float Bh[128][36], Bl[128][36];
    const int tid = threadIdx.x, lane = tid&31, w = tid>>5;
    const int lr = lane>>2, lc = lane&3;
    const int j0 = blockIdx.x*128;
    const int k0 = blockIdx.y*128;
    float d[2][2][4] = {};
    gdep_wait();

    for (int kt = 0; kt < 4; ++kt){
        const int kk = k0 + kt*32;
        {
            int r = tid>>3, c = (tid&7)*4;
            float4 xv = *reinterpret_cast<const float4*>(X + (size_t)r*KC + kk + c);
            float4 hi, lo;
            hi.x=tf32r(xv.x); lo.x=tf32r(xv.x-hi.x);
            hi.y=tf32r(xv.y); lo.y=tf32r(xv.y-hi.y);
            hi.z=tf32r(xv.z); lo.z=tf32r(xv.z-hi.z);
            hi.w=tf32r(xv.w); lo.w=tf32r(xv.w-hi.w);
            *reinterpret_cast<float4*>(&Xh[r][c]) = hi;
            *reinterpret_cast<float4*>(&Xl[r][c]) = lo;
        }
#pragma unroll
        for (int i=0;i<4;i++){
            int f = tid + i*256;
            int r = f>>3, c = (f&7)*4;
            *reinterpret_cast<float4*>(&Bh[r][c]) =
                *reinterpret_cast<const float4*>(Whi + (size_t)(j0+r)*KC + kk + c);
            *reinterpret_cast<float4*>(&Bl[r][c]) =
                *reinterpret_cast<const float4*>(Wlo + (size_t)(j0+r)*KC + kk + c);
        }
        __syncthreads();
#pragma unroll
        for (int k8=0;k8<4;k8++){
            const int co = k8*8;
            unsigned ah[2][4], al[2][4];
#pragma unroll
            for (int mi=0;mi<2;mi++){
                int rb = mi*16 + lr;
                ah[mi][0]=__float_as_uint(Xh[rb  ][co+lc]);
                ah[mi][1]=__float_as_uint(Xh[rb+8][co+lc]);
                ah[mi][2]=__float_as_uint(Xh[rb  ][co+lc+4]);
                ah[mi][3]=__float_as_uint(Xh[rb+8][co+lc+4]);
                al[mi][0]=__float_as_uint(Xl[rb  ][co+lc]);
                al[mi][1]=__float_as_uint(Xl[rb+8][co+lc]);
                al[mi][2]=__float_as_uint(Xl[rb  ][co+lc+4]);
                al[mi][3]=__float_as_uint(Xl[rb+8][co+lc+4]);
            }
#pragma unroll
            for (int nj=0;nj<2;nj++){
                int nb = w*16 + nj*8 + lr;
                unsigned bh0 = __float_as_uint(Bh[nb][co+lc]);
                unsigned bh1 = __float_as_uint(Bh[nb][co+lc+4]);
                unsigned bl0 = __float_as_uint(Bl[nb][co+lc]);
                unsigned bl1 = __float_as_uint(Bl[nb][co+lc+4]);
#pragma unroll
                for (int mi=0;mi<2;mi++){
#define GMMA(AA,B0,B1) asm volatile( \
    "mma.sync.aligned.m16n8k8.row.col.f32.tf32.tf32.f32 " \
    "{%0,%1,%2,%3},{%4,%5,%6,%7},{%8,%9},{%0,%1,%2,%3};" \
    : "+f"(d[mi][nj][0]),"+f"(d[mi][nj][1]),"+f"(d[mi][nj][2]),"+f"(d[mi][nj][3]) \
    : "r"(AA[mi][0]),"r"(AA[mi][1]),"r"(AA[mi][2]),"r"(AA[mi][3]),"r"(B0),"r"(B1))
                    GMMA(ah, bh0, bh1);
                    GMMA(ah, bl0, bl1);
                    GMMA(al, bh0, bh1);
#undef GMMA
                }
            }
        }
        __syncthreads();
    }
    float* out = Cp + blockIdx.y*65536;
#pragma unroll
    for (int mi=0;mi<2;mi++){
#pragma unroll
        for (int nj=0;nj<2;nj++){
            int col = j0 + w*16 + nj*8 + lc*2;
            int m  = mi*16 + lr;
            *reinterpret_cast<float2*>(&out[(size_t)m*2048 + col])     = make_float2(d[mi][nj][0], d[mi][nj][1]);
            *reinterpret_cast<float2*>(&out[(size_t)(m+8)*2048 + col]) = make_float2(d[mi][nj][2], d[mi][nj][3]);
        }
    }
}

__global__ __launch_bounds__(512) void cell0_kernel(int t)
{
    const int b = blockIdx.x, u = threadIdx.x;
    gdep_wait();
    const float* eg = g_embg0 + ((size_t)(b*TT+t))*2048;
    float gi=eg[u], gf=eg[512+u], gg=eg[1024+u], go=eg[1536+u];
#pragma unroll
    for (int s=0;s<8;s++){
        const float* p = g_part0 + s*65536 + b*2048;
        gi += p[u]; gf += p[512+u]; gg += p[1024+u]; go += p[1536+u];
    }
    float c = sigf(gf)*g_c0[b*HH+u] + sigf(gi)*tanh_acc(gg);
    float h = sigf(go)*tanh_acc(c);
    g_c0[b*HH+u] = c;
    g_xcat0[b*KC + 512 + u] = h;   // h0 for next step's gates0
    g_xcat1[b*KC + u]       = h;   // h0 input to gates1 (this step)
}

__global__ __launch_bounds__(512) void cell1_kernel(const float* __restrict__ bq, int t)
{
    const int b = blockIdx.x, u = threadIdx.x;
    __shared__ __align__(16) float h1s[512];
    __shared__ __align__(16) float qpart[4][512];
    gdep_wait();
    float gi=g_bcat1[u], gf=g_bcat1[512+u], gg=g_bcat1[1024+u], go=g_bcat1[1536+u];
#pragma unroll
    for (int s=0;s<8;s++){
        const float* p = g_part1 + s*65536 + b*2048;
        gi += p[u]; gf += p[512+u]; gg += p[1024+u]; go += p[1536+u];
    }
    float c = sigf(gf)*g_c1[b*HH+u] + sigf(gi)*tanh_acc(gg);
    float h = sigf(go)*tanh_acc(c);
    g_c1[b*HH+u] = c;
    g_h1[b*HH+u] = h;
    g_xcat1[b*KC + 512 + u] = h;
    g_Xall[((size_t)(b*TT+t))*KL + u] = tf32r(h);
    h1s[u] = h;
    __syncthreads();
    const int h4 = (u & 127)*4, kp = u >> 7;
    float4 a = make_float4(0.f,0.f,0.f,0.f);
    const float* wb = g_Wqt + (size_t)kp*128*HH + h4;
#pragma unroll 4
    for (int k=0;k<128;k++){
        float4 w4 = *reinterpret_cast<const float4*>(wb + (size_t)k*HH);
        float xv = h1s[kp*128 + k];
        a.x=fmaf(w4.x,xv,a.x); a.y=fmaf(w4.y,xv,a.y);
        a.z=fmaf(w4.z,xv,a.z); a.w=fmaf(w4.w,xv,a.w);
    }
    *reinterpret_cast<float4*>(&qpart[kp][h4]) = a;
    __syncthreads();
    g_qp[b*HH+u] = qpart[0][u]+qpart[1][u]+qpart[2][u]+qpart[3][u] + bq[u];
}

// logits v4: tf32 mma, B rounded in-register (reads raw Wout), 3-stage cp.async; PDL
__global__ __launch_bounds__(256) void logits_mma(
    const float* __restrict__ A, const float* __restrict__ B,
    const float* __restrict__ bias, float* __restrict__ C)
{
    extern __shared__ __align__(16) float smem_l[];
    float (*As)[128][20] = reinterpret_cast<float(*)[128][20]>(smem_l);
    float (*Bs)[128][20] = reinterpret_cast<float(*)[128][20]>(smem_l + 3*128*20);
    const int tid = threadIdx.x, lane = tid&31, w = tid>>5;
    const int wm = (w&3)*32, wn = (w>>2)*64;
    const int m0 = blockIdx.x*128, n0 = blockIdx.y*128;
    const int lr = lane>>2, lc = lane&3;
    float d[2][8][4] = {};
    gdep_wait();

#define STAGE(bufi, kt) do { \
    int kk = (kt)*16; \
    _Pragma("unroll") \
    for (int i=0;i<2;i++){ \
        int f = tid + i*256; int r = f>>2, c = f&3; \
        unsigned dst = (unsigned)__cvta_generic_to_shared(&As[bufi][r][c*4]); \
        const float* src = A + (size_t)(m0+r)*KL + kk + c*4; \
        asm volatile("cp.async.cg.shared.global [%0], [%1], 16;"::"r"(dst),"l"(src)); \
    } \
    _Pragma("unroll") \
    for (int i=0;i<2;i++){ \
        int f = tid + i*256; int r = f>>2, c = f&3; \
        unsigned dst = (unsigned)__cvta_generic_to_shared(&Bs[bufi][r][c*4]); \
        const float* src = B + (size_t)(n0+r)*KL + kk + c*4; \
        asm volatile("cp.async.cg.shared.global [%0], [%1], 16;"::"r"(dst),"l"(src)); \
    } \
    asm volatile("cp.async.commit_group;"); \
} while(0)

    STAGE(0, 0);
    STAGE(1, 1);
    const int KT = KL/16;
    for (int kt=0; kt<KT; ++kt){
        const int buf = kt % 3;
        if (kt == KT-1) asm volatile("cp.async.wait_group 0;");
        else            asm volatile("cp.async.wait_group 1;");
        __syncthreads();
        if (kt+2 < KT) STAGE((kt+2)%3, kt+2);
#pragma unroll
        for (int k8=0;k8<2;k8++){
            const int co = k8*8;
            unsigned a[2][4];
#pragma unroll
            for (int mi=0;mi<2;mi++){
                int rb = wm + mi*16 + lr;
                a[mi][0] = __float_as_uint(As[buf][rb  ][co+lc]);
                a[mi][1] = __float_as_uint(As[buf][rb+8][co+lc]);
                a[mi][2] = __float_as_uint(As[buf][rb  ][co+lc+4]);
                a[mi][3] = __float_as_uint(As[buf][rb+8][co+lc+4]);
            }
#pragma unroll
            for (int nj=0;nj<8;nj++){
                int nb = wn + nj*8 + lr;
                unsigned b0 = __float_as_uint(tf32r(Bs[buf][nb][co+lc]));
                unsigned b1 = __float_as_uint(tf32r(Bs[buf][nb][co+lc+4]));
#pragma unroll
                for (int mi=0;mi<2;mi++){
                    asm volatile(
                      "mma.sync.aligned.m16n8k8.row.col.f32.tf32.tf32.f32 "
                      "{%0,%1,%2,%3},{%4,%5,%6,%7},{%8,%9},{%0,%1,%2,%3};"
                      : "+f"(d[mi][nj][0]),"+f"(d[mi][nj][1]),"+f"(d[mi][nj][2]),"+f"(d[mi][nj][3])
                      : "r"(a[mi][0]),"r"(a[mi][1]),"r"(a[mi][2]),"r"(a[mi][3]),"r"(b0),"r"(b1));
                }
            }
        }
    }
#undef STAGE
    __syncthreads();

    float* ep = smem_l + w*640;
#pragma unroll
    for (int h=0; h<4; h++){
#pragma unroll
        for (int mi=0;mi<2;mi++){
#pragma unroll
            for (int njl=0;njl<2;njl++){
                int nj = h*2 + njl;
                int r0 = mi*16 + lr;
                ep[ r0   *20 + njl*8 + lc*2    ] = d[mi][nj][0];
                ep[ r0   *20 + njl*8 + lc*2 + 1] = d[mi][nj][1];
                ep[(r0+8)*20 + njl*8 + lc*2    ] = d[mi][nj][2];
                ep[(r0+8)*20 + njl*8 + lc*2 + 1] = d[mi][nj][3];
            }
        }
        __syncwarp();
#pragma unroll
        for (int q=0;q<4;q++){
            int idx = q*32 + lane;
            int r = idx>>2, c4 = idx&3;
            float4 vv = *reinterpret_cast<float4*>(&ep[r*20 + c4*4]);
            size_t nn = (size_t)n0 + wn + h*16 + c4*4;
            float4 bb = *reinterpret_cast<const float4*>(&bias[nn]);
            vv.x+=bb.x; vv.y+=bb.y; vv.z+=bb.z; vv.w+=bb.w;
            *reinterpret_cast<float4*>(&C[(size_t)(m0+wm+r)*VV + nn]) = vv;
        }
        __syncwarp();
    }
}

__global__ __launch_bounds__(512) void tail_kernel(float* __restrict__ out)
{
    gdep_wait();
    int idx = blockIdx.x*blockDim.x + threadIdx.x;
    int part = idx / (BB*HH);
    int off  = idx % (BB*HH);
    int b = off / HH, u = off % HH;
    float val;
    if      (part == 0) val = g_xcat1[b*KC + u];
    else if (part == 1) val = g_h1[off];
    else if (part == 2) val = g_c0[off];
    else                val = g_c1[off];
    out[OUT_TAIL_OFF + idx] = val;
}

// PDL launch helper
template <typename K, typename... Args>
static inline void launch_pdl(K kern, dim3 grid, dim3 block, size_t smem, Args... args)
{
    cudaLaunchConfig_t cfg = {};
    cfg.gridDim = grid;
    cfg.blockDim = block;
    cfg.dynamicSmemBytes = smem;
    cfg.stream = 0;
    cudaLaunchAttribute at[1];
    at[0].id = cudaLaunchAttributeProgrammaticStreamSerialization;
    at[0].val.programmaticStreamSerializationAllowed = 1;
    cfg.attrs = at;
    cfg.numAttrs = 1;
    cudaLaunchKernelEx(&cfg, kern, args...);
}

extern "C" void kernel_launch(void* const* d_in, const int* in_sizes, int n_in,
                              void* d_out, int out_size)
{
    const float* enc  = (const float*)d_in[0];
    const int*   tok  = (const int*)  d_in[1];
    const float* emb  = (const float*)d_in[2];
    const float* Wq   = (const float*)d_in[3];
    const float* bq   = (const float*)d_in[4];
    const float* Wk   = (const float*)d_in[5];
    const float* bk   = (const float*)d_in[6];
    const float* v    = (const float*)d_in[7];
    const float* Wih0 = (const float*)d_in[8];
    const float* Whh0 = (const float*)d_in[9];
    const float* bih0 = (const float*)d_in[10];
    const float* bhh0 = (const float*)d_in[11];
    const float* Wih1 = (const float*)d_in[12];
    const float* Whh1 = (const float*)d_in[13];
    const float* bih1 = (const float*)d_in[14];
    const float* bhh1 = (const float*)d_in[15];
    const float* Wout = (const float*)d_in[16];
    const float* bout = (const float*)d_in[17];
    float* out = (float*)d_out;

    float *p_W0hi, *p_W0lo, *p_W1hi, *p_W1lo;
    float *p_xcat0, *p_xcat1, *p_part0, *p_part1, *p_Xall;
    cudaGetSymbolAddress((void**)&p_W0hi,  g_W0hi);
    cudaGetSymbolAddress((void**)&p_W0lo,  g_W0lo);
    cudaGetSymbolAddress((void**)&p_W1hi,  g_W1hi);
    cudaGetSymbolAddress((void**)&p_W1lo,  g_W1lo);
    cudaGetSymbolAddress((void**)&p_xcat0, g_xcat0);
    cudaGetSymbolAddress((void**)&p_xcat1, g_xcat1);
    cudaGetSymbolAddress((void**)&p_part0, g_part0);
    cudaGetSymbolAddress((void**)&p_part1, g_part1);
    cudaGetSymbolAddress((void**)&p_Xall,  g_Xall);

    cudaFuncSetAttribute(logits_mma, cudaFuncAttributeMaxDynamicSharedMemorySize, 3*2*128*20*4);

    // setup (plain launches = fully serialized; embg needs init's WE hi/lo)
    init_kernel<<<2048, 256>>>(Wih0, Whh0, bih0, bhh0, Wih1, Whh1, bih1, bhh1, Wq, bq);
    cvt_enc<<<2048, 256>>>(enc);
    keyproj_mma<<<dim3(64, 4), 256>>>(enc, Wk, bk);
    embg_mma<<<dim3(16, 128), 256>>>(emb, tok);

    for (int t = 0; t < TT; ++t){
        launch_pdl(scores_kernel, dim3(BB, 32), dim3(256), 0, v);
        launch_pdl(smctx_kernel,  dim3(BB, 8),  dim3(256), 0, t);
        launch_pdl(gates_mma, dim3(16, 8), dim3(256), 0,
                   (const float*)p_xcat0, (const float*)p_W0hi, (const float*)p_W0lo, p_part0);
        launch_pdl(cell0_kernel, dim3(BB), dim3(512), 0, t);
        launch_pdl(gates_mma, dim3(16, 8), dim3(256), 0,
                   (const float*)p_xcat1, (const float*)p_W1hi, (const float*)p_W1lo, p_part1);
        launch_pdl(cell1_kernel, dim3(BB), dim3(512), 0, bq, t);
    }

    {   // logits = Xall @ Wout^T (B rounded in-register) + bout
        launch_pdl(logits_mma, dim3((BB*TT)/128, VV/128), dim3(256), (size_t)(3*2*128*20*4),
                   (const float*)p_Xall, Wout, bout, out);
    }
    launch_pdl(tail_kernel, dim3(128), dim3(512), 0, out);
}